// round 13
// baseline (speedup 1.0000x reference)
#include <cuda_runtime.h>
#include <cuda_fp16.h>
#include <math.h>
#include <stdint.h>

// Problem constants
#define BB    8
#define CC    512
#define HH    56
#define WW_   56
#define HWSZ  3136
#define WS_   7
#define SS_   3
#define NH_   16
#define HD_   32
#define T_    49
#define NW_   64
#define BW_   512          // BB * NW_
#define NTOK  25088        // BW_ * T_
#define L_    64

// ---------------- scratch (device globals; no runtime alloc) ----------------
__device__ __align__(16) __half g_vin [512 * 256];
__device__ __align__(16) __half g_vec [BW_ * CC];
__device__ __align__(16) __half g_tok [NTOK * CC];
__device__ __align__(16) __half g_qkv [NTOK * 3 * CC];
__device__ __align__(16) __half g_o1  [NTOK * CC];
__device__ __align__(16) __half g_w2  [NTOK * CC];
__device__ float  g_skipa[NTOK * CC];       // skip1 [B,HW,C] full fp32
__device__ __align__(16) __half g_pq  [NTOK * CC];
__device__ __align__(16) __half g_q2  [NTOK * CC];
__device__ __align__(16) __half g_kv2 [BW_ * 2 * CC];   // [B*L, 1024]: k | v
__device__ __align__(16) __half g_co1 [NTOK * CC];
__device__ __align__(16) __half g_co2 [NTOK * CC];
__device__ float  g_skip2[NTOK * CC];       // full fp32
__device__ __align__(16) __half g_skip2r[NTOK * CC]; // fp16 copy for GEMM
__device__ __align__(16) __half g_ffh [NTOK * 4 * CC];
__device__ __align__(16) __half g_ffo [NTOK * CC];
__device__ float  g_bias[NH_ * T_ * T_];

// transposed (fp16) weights: [N, K] K-contiguous
__device__ __align__(16) __half g_tmw_t  [512 * 256];
__device__ __align__(16) __half g_qkvw_t [1536 * 512];
__device__ __align__(16) __half g_wprw_t [512 * 512];
__device__ __align__(16) __half g_cain_t [1536 * 512];
__device__ __align__(16) __half g_caout_t[512 * 512];
__device__ __align__(16) __half g_ff1_t  [2048 * 512];
__device__ __align__(16) __half g_ff2_t  [512 * 2048];

// ---------------- helpers ----------------
__device__ __forceinline__ float gelu_exact(float x) {
    return 0.5f * x * (1.0f + erff(x * 0.70710678118654752f));
}
__device__ __forceinline__ uint32_t s2u(const void* p) {
    uint32_t a;
    asm("{ .reg .u64 t; cvta.to.shared.u64 t, %1; cvt.u32.u64 %0, t; }"
        : "=r"(a) : "l"(p));
    return a;
}

// warp-wide mean/rstd from per-lane partials (row length n)
__device__ __forceinline__ void warp_meanvar(float s, float ss, int n,
                                             float* mu, float* rstd) {
    #pragma unroll
    for (int o = 16; o > 0; o >>= 1) {
        s  += __shfl_xor_sync(0xffffffffu, s,  o);
        ss += __shfl_xor_sync(0xffffffffu, ss, o);
    }
    float m = s / n;
    *mu = m;
    *rstd = rsqrtf(ss / n - m * m + 1e-5f);
}

// ---------------- fp16 mma.sync GEMM (3-stage pipeline + ldmatrix) ----------
#define EPI_NONE  0
#define EPI_GELU  1
#define EPI_SCALE 2

#define LDPAD_H 40
#define TILEH (128 * LDPAD_H)            // halves per tile
#define TGEMM_SMEM (6 * TILEH * 2)       // 3 stages x (A+B), bytes = 61440

__device__ __forceinline__ void mma_f16(float* c, const uint32_t* a,
                                        const uint32_t* b) {
    asm volatile(
        "mma.sync.aligned.m16n8k16.row.col.f32.f16.f16.f32 "
        "{%0,%1,%2,%3}, {%4,%5,%6,%7}, {%8,%9}, {%0,%1,%2,%3};"
        : "+f"(c[0]), "+f"(c[1]), "+f"(c[2]), "+f"(c[3])
        : "r"(a[0]), "r"(a[1]), "r"(a[2]), "r"(a[3]),
          "r"(b[0]), "r"(b[1]));
}

#define LDSM_X4(r0, r1, r2, r3, addr) \
    asm volatile("ldmatrix.sync.aligned.m8n8.x4.shared.b16 {%0,%1,%2,%3}, [%4];" \
        : "=r"(r0), "=r"(r1), "=r"(r2), "=r"(r3) : "r"(addr))

__device__ __forceinline__ void store2(float* p, float a, float b) {
    *(float2*)p = make_float2(a, b);
}
__device__ __forceinline__ void store2(__half* p, float a, float b) {
    *(__half2*)p = __floats2half2_rn(a, b);
}

template <int EPI, typename OutT>
__global__ __launch_bounds__(256, 2)
void tgemm(const __half* __restrict__ A, const __half* __restrict__ W,
           const float* __restrict__ bias, OutT* __restrict__ C,
           int M, int N, int K, float alpha) {
    extern __shared__ __half smh[];
    __half* Abuf = smh;                  // [3][128][LDPAD_H]
    __half* Bbuf = smh + 3 * TILEH;      // [3][128][LDPAD_H]
    const uint32_t sm_a = s2u(Abuf), sm_b = s2u(Bbuf);

    const int tid = threadIdx.x;
    const int wid = tid >> 5, lane = tid & 31;
    const int m0 = blockIdx.y << 7, n0 = blockIdx.x << 7;
    const int wm = wid & 3, wn = wid >> 2;
    const int m_off = wm << 5;
    const int n_off = wn << 6;

    const __half* Abase = A + (size_t)m0 * K;
    const __half* Wbase = W + (size_t)n0 * K;
    const int NC = K >> 5;

    const int seg = tid & 3;
    const int lr0 = tid >> 2;

    auto load_chunk = [&](int c, int sel) {
        uint32_t ab = sm_a + sel * (TILEH * 2);
        uint32_t bb = sm_b + sel * (TILEH * 2);
        const __half* As = Abase + c * 32 + seg * 8;
        const __half* Ws = Wbase + c * 32 + seg * 8;
        #pragma unroll
        for (int i = 0; i < 2; i++) {
            int r = lr0 + (i << 6);
            uint32_t so = (uint32_t)(r * (LDPAD_H * 2) + seg * 16);
            asm volatile("cp.async.cg.shared.global [%0], [%1], 16;"
                         :: "r"(ab + so), "l"(As + (size_t)r * K));
            asm volatile("cp.async.cg.shared.global [%0], [%1], 16;"
                         :: "r"(bb + so), "l"(Ws + (size_t)r * K));
        }
        asm volatile("cp.async.commit_group;" ::: "memory");
    };

    const int lm = lane >> 3, lr = lane & 7;
    uint32_t a_off[2], b_off[4];
    #pragma unroll
    for (int mt = 0; mt < 2; mt++) {
        int row = m_off + mt * 16 + lr + (lm & 1) * 8;
        int koff = (lm >> 1) * 8;
        a_off[mt] = (uint32_t)((row * LDPAD_H + koff) * 2);
    }
    #pragma unroll
    for (int g = 0; g < 4; g++) {
        int row = n_off + (2 * g + (lm >> 1)) * 8 + lr;
        int koff = (lm & 1) * 8;
        b_off[g] = (uint32_t)((row * LDPAD_H + koff) * 2);
    }

    float acc[2][8][4];
    #pragma unroll
    for (int i = 0; i < 2; i++)
        #pragma unroll
        for (int j = 0; j < 8; j++)
            #pragma unroll
            for (int q = 0; q < 4; q++) acc[i][j][q] = 0.f;

    load_chunk(0, 0);
    if (NC > 1) load_chunk(1, 1);

    const int qr = lane >> 2, qc = lane & 3;
    int sel = 0;

    for (int c = 0; c < NC; c++) {
        if (c + 1 < NC)
            asm volatile("cp.async.wait_group 1;" ::: "memory");
        else
            asm volatile("cp.async.wait_group 0;" ::: "memory");
        __syncthreads();
        if (c + 2 < NC) {
            int s2 = sel + 2; if (s2 >= 3) s2 -= 3;
            load_chunk(c + 2, s2);
        }

        const uint32_t abase = sm_a + sel * (TILEH * 2);
        const uint32_t bbase = sm_b + sel * (TILEH * 2);

        #pragma unroll
        for (int ks = 0; ks < 2; ks++) {
            const uint32_t kb = ks * 32;
            uint32_t a[2][4], b[8][2];
            #pragma unroll
            for (int mt = 0; mt < 2; mt++)
                LDSM_X4(a[mt][0], a[mt][1], a[mt][2], a[mt][3],
                        abase + a_off[mt] + kb);
            #pragma unroll
            for (int g = 0; g < 4; g++)
                LDSM_X4(b[2 * g][0], b[2 * g][1], b[2 * g + 1][0], b[2 * g + 1][1],
                        bbase + b_off[g] + kb);
            #pragma unroll
            for (int mt = 0; mt < 2; mt++)
                #pragma unroll
                for (int nt = 0; nt < 8; nt++)
                    mma_f16(acc[mt][nt], a[mt], b[nt]);
        }
        if (++sel >= 3) sel = 0;
    }

    #pragma unroll
    for (int mt = 0; mt < 2; mt++) {
        #pragma unroll
        for (int half = 0; half < 2; half++) {
            int row = m0 + m_off + mt * 16 + qr + half * 8;
            OutT* Cp = C + (size_t)row * N + n0 + n_off;
            #pragma unroll
            for (int nt = 0; nt < 8; nt++) {
                int col = nt * 8 + qc * 2;
                float v0 = acc[mt][nt][half * 2 + 0] + bias[n0 + n_off + col];
                float v1 = acc[mt][nt][half * 2 + 1] + bias[n0 + n_off + col + 1];
                if (EPI == EPI_GELU)  { v0 = gelu_exact(v0); v1 = gelu_exact(v1); }
                if (EPI == EPI_SCALE) { v0 *= alpha; v1 *= alpha; }
                store2(Cp + col, v0, v1);
            }
        }
    }
}

// ---------------- weight transpose + fp16 ----------------
__global__ __launch_bounds__(256)
void transpose_w(const float* __restrict__ W, __half* __restrict__ Wt,
                 int K, int N) {
    __shared__ float tile[32][33];
    int kb = blockIdx.y * 32, nb = blockIdx.x * 32;
    int tx = threadIdx.x & 31, ty = threadIdx.x >> 5;
    #pragma unroll
    for (int i = 0; i < 32; i += 8)
        tile[ty + i][tx] = W[(size_t)(kb + ty + i) * N + nb + tx];
    __syncthreads();
    #pragma unroll
    for (int i = 0; i < 32; i += 8)
        Wt[(size_t)(nb + ty + i) * K + kb + tx] = __float2half_rn(tile[tx][ty + i]);
}

__global__ void half_copy(const float* __restrict__ in, __half* __restrict__ o, int n) {
    int i = blockIdx.x * 256 + threadIdx.x;
    if (i < n) o[i] = __float2half_rn(in[i]);
}

// ---------------- relative-position bias precompute ----------------
__global__ void bias_kernel(const float* __restrict__ w1, const float* __restrict__ b1,
                            const float* __restrict__ w2, const float* __restrict__ b2) {
    int pair = blockIdx.x;
    int q = pair / T_, k = pair % T_;
    float d0 = (float)(q / WS_ - k / WS_);
    float d1 = (float)(q % WS_ - k % WS_);
    float r0 = (d0 > 0.f ? 1.f : (d0 < 0.f ? -1.f : 0.f)) * log1pf(fabsf(d0));
    float r1 = (d1 > 0.f ? 1.f : (d1 < 0.f ? -1.f : 0.f)) * log1pf(fabsf(d1));
    int tid = threadIdx.x;
    __shared__ float hbuf[256];
    float hv = r0 * w1[tid] + r1 * w1[256 + tid] + b1[tid];
    hbuf[tid] = fmaxf(hv, 0.f);
    __syncthreads();
    if (tid < NH_) {
        float s = b2[tid];
        #pragma unroll 8
        for (int j = 0; j < 256; j++) s += hbuf[j] * w2[j * NH_ + tid];
        g_bias[tid * (T_ * T_) + pair] = s;
    }
}

// ---------------- roll(-3,-3) + unfold (warp-per-row) ----------------
__global__ __launch_bounds__(256)
void unfold_kernel(const float* __restrict__ visual) {
    int r = blockIdx.x * 8 + (threadIdx.x >> 5);
    int lane = threadIdx.x & 31;
    int bw = r / T_, t = r % T_;
    int b = bw / NW_, win = bw % NW_, wh = win >> 3, ww = win & 7;
    int h = (wh * WS_ + t / WS_ + SS_) % HH;
    int w = (ww * WS_ + t % WS_ + SS_) % WW_;
    int hw = h * WW_ + w;
    int c0 = lane * 16;
    const float* vp = visual + (size_t)(b * CC + c0) * HWSZ + hw;
    __half* tp = g_tok + (size_t)r * CC + c0;
    #pragma unroll
    for (int i = 0; i < 16; i += 2) {
        float v0 = vp[(size_t)i * HWSZ];
        float v1 = vp[(size_t)(i + 1) * HWSZ];
        *(__half2*)(tp + i) = __floats2half2_rn(v0, v1);
    }
}

// ---------------- window attention (register-blocked) ----------------
#define SQS 36   // padded row stride (floats)
__global__ __launch_bounds__(256)
void win_attn(const float* __restrict__ tau) {
    int bw = blockIdx.x >> 4;
    int hh = blockIdx.x & 15;
    int tid = threadIdx.x;

    __shared__ __align__(16) float sq[52 * SQS], sk[52 * SQS], sv[52 * SQS];
    __shared__ float ss[50 * 50];
    __shared__ float nq[52], nk[52];
    __shared__ int   rg[T_];

    for (int i = tid; i < 3 * 32; i += 256) {
        int r = 49 + i / 32, c = i % 32;
        sq[r * SQS + c] = 0.f; sk[r * SQS + c] = 0.f; sv[r * SQS + c] = 0.f;
    }

    size_t base = (size_t)(bw * T_) * (3 * CC);
    for (int idx = tid; idx < T_ * HD_; idx += 256) {
        int t = idx / HD_, d = idx % HD_;
        size_t ro = base + (size_t)t * (3 * CC) + hh * HD_ + d;
        sq[t * SQS + d] = __half2float(g_qkv[ro]);
        sk[t * SQS + d] = __half2float(g_qkv[ro + CC]);
        sv[t * SQS + d] = __half2float(g_qkv[ro + 2 * CC]);
    }
    int win = bw & 63, wh = win >> 3, ww = win & 7;
    if (tid < T_) {
        int row = wh * WS_ + tid / WS_;
        int col = ww * WS_ + tid % WS_;
        int rh = row < 49 ? 0 : (row < 53 ? 1 : 2);
        int rw = col < 49 ? 0 : (col < 53 ? 1 : 2);
        rg[tid] = rh * 3 + rw;
    }
    __syncthreads();

    if (tid < 52) {
        if (tid < T_) {
            float s1 = 0.f, s2 = 0.f;
            #pragma unroll
            for (int d = 0; d < HD_; d++) {
                float a = sq[tid * SQS + d], b = sk[tid * SQS + d];
                s1 += a * a; s2 += b * b;
            }
            nq[tid] = sqrtf(s1); nk[tid] = sqrtf(s2);
        } else {
            nq[tid] = 1.f; nk[tid] = 1.f;
        }
    }
    __syncthreads();

    float tauh = fmaxf(tau[hh], 0.01f);
    const float* bh = &g_bias[hh * (T_ * T_)];
    if (tid < 169) {
        int q0 = (tid / 13) * 4, k0 = (tid % 13) * 4;
        float acc[4][4];
        #pragma unroll
        for (int i = 0; i < 4; i++)
            #pragma unroll
            for (int j = 0; j < 4; j++) acc[i][j] = 0.f;
        #pragma unroll
        for (int d4 = 0; d4 < 8; d4++) {
            float4 qv[4], kv[4];
            #pragma unroll
            for (int i = 0; i < 4; i++)
                qv[i] = *(const float4*)&sq[(q0 + i) * SQS + d4 * 4];
            #pragma unroll
            for (int j = 0; j < 4; j++)
                kv[j] = *(const float4*)&sk[(k0 + j) * SQS + d4 * 4];
            #pragma unroll
            for (int i = 0; i < 4; i++)
                #pragma unroll
                for (int j = 0; j < 4; j++)
                    acc[i][j] += qv[i].x * kv[j].x + qv[i].y * kv[j].y
                               + qv[i].z * kv[j].z + qv[i].w * kv[j].w;
        }
        #pragma unroll
        for (int i = 0; i < 4; i++) {
            int q = q0 + i;
            if (q >= T_) break;
            #pragma unroll
            for (int j = 0; j < 4; j++) {
                int k = k0 + j;
                if (k >= T_) continue;
                float s = acc[i][j] / fmaxf(nq[q] * nk[k], 1e-6f) / tauh
                        + bh[q * T_ + k];
                if (rg[q] != rg[k]) s -= 100.0f;
                ss[q * 50 + k] = s;
            }
        }
    }
    __syncthreads();

    if (tid < T_) {
        float m = -1e30f;
        for (int k = 0; k < T_; k++) m = fmaxf(m, ss[tid * 50 + k]);
        float sum = 0.f;
        for (int k = 0; k < T_; k++) {
            float e = expf(ss[tid * 50 + k] - m);
            ss[tid * 50 + k] = e; sum += e;
        }
        float inv = 1.f / sum;
        for (int k = 0; k < T_; k++) ss[tid * 50 + k] *= inv;
    }
    __syncthreads();

    if (tid < 200) {
        int t0 = (tid / 8) * 2, d4 = tid % 8;
        float4 a0 = make_float4(0.f, 0.f, 0.f, 0.f), a1 = a0;
        for (int k = 0; k < T_; k++) {
            float s0 = ss[t0 * 50 + k];
            float s1 = ss[(t0 + 1) * 50 + k];
            float4 v = *(const float4*)&sv[k * SQS + d4 * 4];
            a0.x += s0 * v.x; a0.y += s0 * v.y; a0.z += s0 * v.z; a0.w += s0 * v.w;
            a1.x += s1 * v.x; a1.y += s1 * v.y; a1.z += s1 * v.z; a1.w += s1 * v.w;
        }
        __half* op = g_o1 + (size_t)(bw * T_ + t0) * CC + hh * HD_ + d4 * 4;
        ((__half2*)op)[0] = __floats2half2_rn(a0.x, a0.y);
        ((__half2*)op)[1] = __floats2half2_rn(a0.z, a0.w);
        if (t0 + 1 < T_) {
            __half* op1 = op + CC;
            ((__half2*)op1)[0] = __floats2half2_rn(a1.x, a1.y);
            ((__half2*)op1)[1] = __floats2half2_rn(a1.z, a1.w);
        }
    }
}

// ---------------- fold+roll(+3) + LN1 + residual (warp-per-row) -------------
__global__ __launch_bounds__(256)
void merge_ln1(const float* __restrict__ visual,
               const float* __restrict__ g, const float* __restrict__ bt) {
    int pos = blockIdx.x * 8 + (threadIdx.x >> 5);
    int lane = threadIdx.x & 31;
    int b = pos / HWSZ, hw = pos % HWSZ;
    int h = hw / WW_, w = hw % WW_;
    int hp = (h + HH - SS_) % HH, wp = (w + WW_ - SS_) % WW_;
    int rm = (b * NW_ + (hp / WS_) * 8 + (wp / WS_)) * T_ + (hp % WS_) * WS_ + (wp % WS_);

    int c0 = lane * 16;
    float x[16];
    const __half* wrow = g_w2 + (size_t)rm * CC + c0;
    #pragma unroll
    for (int i = 0; i < 16; i += 2) {
        __half2 h2 = *(const __half2*)(wrow + i);
        x[i] = __low2float(h2); x[i + 1] = __high2float(h2);
    }
    float s = 0.f, ss = 0.f;
    #pragma unroll
    for (int i = 0; i < 16; i++) { s += x[i]; ss += x[i] * x[i]; }
    float mu, rstd;
    warp_meanvar(s, ss, CC, &mu, &rstd);

    const float* vp = visual + (size_t)(b * CC + c0) * HWSZ + hw;
    float o[16];
    #pragma unroll
    for (int i = 0; i < 16; i++) {
        int c = c0 + i;
        o[i] = (x[i] - mu) * rstd * g[c] + bt[c] + vp[(size_t)i * HWSZ];
    }
    float* sp = g_skipa + (size_t)pos * CC + c0;
    #pragma unroll
    for (int i = 0; i < 16; i += 4)
        *(float4*)(sp + i) = make_float4(o[i], o[i+1], o[i+2], o[i+3]);
    __half* pp = g_pq + (size_t)rm * CC + c0;
    #pragma unroll
    for (int i = 0; i < 16; i += 2)
        *(__half2*)(pp + i) = __floats2half2_rn(o[i], o[i + 1]);
}

// ---------------- cross attention (register-blocked) ----------------
__global__ __launch_bounds__(256)
void ca_attn() {
    int bw = blockIdx.x >> 4;
    int hh = blockIdx.x & 15;
    int bkv = bw & 7;
    int tid = threadIdx.x;

    __shared__ __align__(16) float sq[52 * SQS], sk[L_ * SQS], sv[L_ * SQS];
    __shared__ float ss[50 * 65];

    for (int i = tid; i < 3 * 32; i += 256) {
        int r = 49 + i / 32, c = i % 32;
        sq[r * SQS + c] = 0.f;
    }
    for (int idx = tid; idx < T_ * HD_; idx += 256) {
        int t = idx / HD_, d = idx % HD_;
        sq[t * SQS + d] = __half2float(g_q2[(size_t)(bw * T_ + t) * CC + hh * HD_ + d]);
    }
    for (int idx = tid; idx < L_ * HD_; idx += 256) {
        int l = idx / HD_, d = idx % HD_;
        size_t ro = (size_t)(bkv * L_ + l) * (2 * CC) + hh * HD_ + d;
        sk[l * SQS + d] = __half2float(g_kv2[ro]);
        sv[l * SQS + d] = __half2float(g_kv2[ro + CC]);
    }
    __syncthreads();

    if (tid < 208) {
        int q0 = (tid / 16) * 4, l0 = (tid % 16) * 4;
        float acc[4][4];
        #pragma unroll
        for (int i = 0; i < 4; i++)
            #pragma unroll
            for (int j = 0; j < 4; j++) acc[i][j] = 0.f;
        #pragma unroll
        for (int d4 = 0; d4 < 8; d4++) {
            float4 qv[4], kv[4];
            #pragma unroll
            for (int i = 0; i < 4; i++)
                qv[i] = *(const float4*)&sq[(q0 + i) * SQS + d4 * 4];
            #pragma unroll
            for (int j = 0; j < 4; j++)
                kv[j] = *(const float4*)&sk[(l0 + j) * SQS + d4 * 4];
            #pragma unroll
            for (int i = 0; i < 4; i++)
                #pragma unroll
                for (int j = 0; j < 4; j++)
                    acc[i][j] += qv[i].x * kv[j].x + qv[i].y * kv[j].y
                               + qv[i].z * kv[j].z + qv[i].w * kv[j].w;
        }
        #pragma unroll
        for (int i = 0; i < 4; i++) {
            int q = q0 + i;
            if (q >= T_) break;
            #pragma unroll
            for (int j = 0; j < 4; j++)
                ss[q * 65 + l0 + j] = acc[i][j];
        }
    }
    __syncthreads();

    if (tid < T_) {
        float m = -1e30f;
        for (int l = 0; l < L_; l++) m = fmaxf(m, ss[tid * 65 + l]);
        float sum = 0.f;
        for (int l = 0; l < L_; l++) {
            float e = expf(ss[tid * 65 + l] - m);
            ss[tid * 65 + l] = e; sum += e;
        }
        float inv = 1.f / sum;
        for (int l = 0; l < L_; l++) ss[tid * 65 + l] *= inv;
    }
    __syncthreads();

    if (tid < 200) {
        int t0 = (tid / 8) * 2, d4 = tid % 8;
        float4 a0 = make_float4(0.f, 0.f, 0.f, 0.f), a1 = a0;
        for (int l = 0; l < L_; l++) {
            float s0 = ss[t0 * 65 + l];
            float s1 = ss[(t0 + 1) * 65 + l];
            float4 v = *(const float4*)&sv[l * SQS + d4 * 4];
            a0.x += s0 * v.x; a0.y += s0 * v.y; a0.z += s0 * v.z; a0.w += s0 * v.w;
            a1.x += s1 * v.x; a1.y += s1 * v.y; a1.z += s1 * v.z; a1.w += s1 * v.w;
        }
        __half* op = g_co1 + (size_t)(bw * T_ + t0) * CC + hh * HD_ + d4 * 4;
        ((__half2*)op)[0] = __floats2half2_rn(a0.x, a0.y);
        ((__half2*)op)[1] = __floats2half2_rn(a0.z, a0.w);
        if (t0 + 1 < T_) {
            __half* op1 = op + CC;
            ((__half2*)op1)[0] = __floats2half2_rn(a1.x, a1.y);
            ((__half2*)op1)[1] = __floats2half2_rn(a1.z, a1.w);
        }
    }
}

// ---------------- LN2 + fold+roll(+3) + residual (warp-per-row) -------------
__global__ __launch_bounds__(256)
void ca_ln2(const float* __restrict__ g, const float* __restrict__ bt) {
    int r = blockIdx.x * 8 + (threadIdx.x >> 5);
    int lane = threadIdx.x & 31;
    int bw = r / T_, t = r % T_;
    int b = bw / NW_, win = bw % NW_, wh = win >> 3, ww = win & 7;
    int h = (wh * WS_ + t / WS_ + SS_) % HH;
    int w = (ww * WS_ + t % WS_ + SS_) % WW_;
    int pos = b * HWSZ + h * WW_ + w;

    int c0 = lane * 16;
    float x[16];
    const __half* crow = g_co2 + (size_t)r * CC + c0;
    #pragma unroll
    for (int i = 0; i < 16; i += 2) {
        __half2 h2 = *(const __half2*)(crow + i);
        x[i] = __low2float(h2); x[i + 1] = __high2float(h2);
    }
    float s = 0.f, ss = 0.f;
    #pragma unroll
    for (int i = 0; i < 16; i++) { s += x[i]; ss += x[i] * x[i]; }
    float mu, rstd;
    warp_meanvar(s, ss, CC, &mu, &rstd);

    const float* sa = g_skipa + (size_t)pos * CC + c0;
    float o[16];
    #pragma unroll
    for (int i = 0; i < 16; i += 4) {
        float4 sv4 = *(const float4*)(sa + i);
        o[i]     = (x[i]     - mu) * rstd * g[c0 + i]     + bt[c0 + i]     + sv4.x;
        o[i + 1] = (x[i + 1] - mu) * rstd * g[c0 + i + 1] + bt[c0 + i + 1] + sv4.y;
        o[i + 2] = (x[i + 2] - mu) * rstd * g[c0 + i + 2] + bt[c0 + i + 2] + sv4.z;
        o[i + 3] = (x[i + 3] - mu) * rstd * g[c0 + i + 3] + bt[c0 + i + 3] + sv4.w;
    }
    float* sp = g_skip2 + (size_t)pos * CC + c0;
    #pragma unroll
    for (int i = 0; i < 16; i += 4)
        *(float4*)(sp + i) = make_float4(o[i], o[i+1], o[i+2], o[i+3]);
    __half* rp = g_skip2r + (size_t)pos * CC + c0;
    #pragma unroll
    for (int i = 0; i < 16; i += 2)
        *(__half2*)(rp + i) = __floats2half2_rn(o[i], o[i + 1]);
}

// ---------------- LN3(ff) + skip2 -> out [B,C,H,W] (warp-per-row) -----------
__global__ __launch_bounds__(256)
void final_kernel(float* __restrict__ out,
                  const float* __restrict__ g, const float* __restrict__ bt) {
    int pos = blockIdx.x * 8 + (threadIdx.x >> 5);
    int lane = threadIdx.x & 31;
    int b = pos / HWSZ, hw = pos % HWSZ;

    int c0 = lane * 16;
    float x[16];
    const __half* frow = g_ffo + (size_t)pos * CC + c0;
    #pragma unroll
    for (int i = 0; i < 16; i += 2) {
        __half2 h2 = *(const __half2*)(frow + i);
        x[i] = __low2float(h2); x[i + 1] = __high2float(h2);
    }
    float s = 0.f, ss = 0.f;
    #pragma unroll
    for (int i = 0; i < 16; i++) { s += x[i]; ss += x[i] * x[i]; }
    float mu, rstd;
    warp_meanvar(s, ss, CC, &mu, &rstd);

    const float* sp = g_skip2 + (size_t)pos * CC + c0;
    float* op = out + (size_t)(b * CC + c0) * HWSZ + hw;
    #pragma unroll
    for (int i = 0; i < 16; i++) {
        float v = (x[i] - mu) * rstd * g[c0 + i] + bt[c0 + i];
        op[(size_t)i * HWSZ] = sp[i] + v;
    }
}

// ---------------- launch ----------------
extern "C" void kernel_launch(void* const* d_in, const int* in_sizes, int n_in,
                              void* d_out, int out_size) {
    const float* visual   = (const float*)d_in[0];
    const float* vector   = (const float*)d_in[1];
    const float* tm_w     = (const float*)d_in[2];
    const float* tm_b     = (const float*)d_in[3];
    const float* ln1_g    = (const float*)d_in[4];
    const float* ln1_b    = (const float*)d_in[5];
    const float* ln2_g    = (const float*)d_in[6];
    const float* ln2_b    = (const float*)d_in[7];
    const float* ln3_g    = (const float*)d_in[8];
    const float* ln3_b    = (const float*)d_in[9];
    const float* qkv_w    = (const float*)d_in[10];
    const float* qkv_b    = (const float*)d_in[11];
    const float* wproj_w  = (const float*)d_in[12];
    const float* wproj_b  = (const float*)d_in[13];
    const float* meta_w1  = (const float*)d_in[14];
    const float* meta_b1  = (const float*)d_in[15];
    const float* meta_w2  = (const float*)d_in[16];
    const float* meta_b2  = (const float*)d_in[17];
    const float* tau      = (const float*)d_in[18];
    const float* ca_in_w  = (const float*)d_in[19];
    const float* ca_in_b  = (const float*)d_in[20];
    const float* ca_out_w = (const float*)d_in[21];
    const float* ca_out_b = (const float*)d_in[22];
    const float* ff_w1    = (const float*)d_in[23];
    const float* ff_b1    = (const float*)d_in[24];
    const float* ff_w2    = (const float*)d_in[25];
    const float* ff_b2    = (const float*)d_in[26];
    float* out = (float*)d_out;

    __half *vin, *vec, *tok, *o1, *pq, *co1, *sk2r, *ffh;
    __half *qkv, *w2, *q2, *kv2, *co2, *ffo;
    __half *tmwt, *qkvwt, *wprwt, *caint, *caoutt, *ff1t, *ff2t;
    cudaGetSymbolAddress((void**)&vin,   g_vin);
    cudaGetSymbolAddress((void**)&vec,   g_vec);
    cudaGetSymbolAddress((void**)&tok,   g_tok);
    cudaGetSymbolAddress((void**)&qkv,   g_qkv);
    cudaGetSymbolAddress((void**)&o1,    g_o1);
    cudaGetSymbolAddress((void**)&w2,    g_w2);
    cudaGetSymbolAddress((void**)&pq,    g_pq);
    cudaGetSymbolAddress((void**)&q2,    g_q2);
    cudaGetSymbolAddress((void**)&kv2,   g_kv2);
    cudaGetSymbolAddress((void**)&co1,   g_co1);
    cudaGetSymbolAddress((void**)&co2,   g_co2);
    cudaGetSymbolAddress((void**)&sk2r,  g_skip2r);
    cudaGetSymbolAddress((void**)&ffh,   g_ffh);
    cudaGetSymbolAddress((void**)&ffo,   g_ffo);
    cudaGetSymbolAddress((void**)&tmwt,  g_tmw_t);
    cudaGetSymbolAddress((void**)&qkvwt, g_qkvw_t);
    cudaGetSymbolAddress((void**)&wprwt, g_wprw_t);
    cudaGetSymbolAddress((void**)&caint, g_cain_t);
    cudaGetSymbolAddress((void**)&caoutt,g_caout_t);
    cudaGetSymbolAddress((void**)&ff1t,  g_ff1_t);
    cudaGetSymbolAddress((void**)&ff2t,  g_ff2_t);

    cudaFuncSetAttribute((const void*)tgemm<EPI_NONE,  __half>, cudaFuncAttributeMaxDynamicSharedMemorySize, TGEMM_SMEM);
    cudaFuncSetAttribute((const void*)tgemm<EPI_GELU,  __half>, cudaFuncAttributeMaxDynamicSharedMemorySize, TGEMM_SMEM);
    cudaFuncSetAttribute((const void*)tgemm<EPI_SCALE, __half>, cudaFuncAttributeMaxDynamicSharedMemorySize, TGEMM_SMEM);

    // weight transposes (+fp16 rounding)
    transpose_w<<<dim3(16,  8), 256>>>(tm_w,     tmwt,  256,  512);
    transpose_w<<<dim3(48, 16), 256>>>(qkv_w,    qkvwt, 512, 1536);
    transpose_w<<<dim3(16, 16), 256>>>(wproj_w,  wprwt, 512,  512);
    transpose_w<<<dim3(48, 16), 256>>>(ca_in_w,  caint, 512, 1536);
    transpose_w<<<dim3(16, 16), 256>>>(ca_out_w, caoutt,512,  512);
    transpose_w<<<dim3(64, 16), 256>>>(ff_w1,    ff1t,  512, 2048);
    transpose_w<<<dim3(16, 64), 256>>>(ff_w2,    ff2t, 2048,  512);
    half_copy<<<512, 256>>>(vector, vin, 512 * 256);

    bias_kernel<<<T_ * T_, 256>>>(meta_w1, meta_b1, meta_w2, meta_b2);

    // vec = gelu(vector @ tm_w + tm_b)
    tgemm<EPI_GELU, __half><<<dim3(4, 4), 256, TGEMM_SMEM>>>(vin, tmwt, tm_b, vec, 512, 512, 256, 0.f);
    // K2|V2 fused
    tgemm<EPI_NONE, __half><<<dim3(8, 4), 256, TGEMM_SMEM>>>(vec, caint + 512 * 512, ca_in_b + 512, kv2, 512, 1024, 512, 0.f);

    unfold_kernel<<<NTOK / 8, 256>>>(visual);
    tgemm<EPI_NONE, __half><<<dim3(12, 196), 256, TGEMM_SMEM>>>(tok, qkvwt, qkv_b, qkv, NTOK, 3 * CC, CC, 0.f);
    win_attn<<<BW_ * NH_, 256>>>(tau);
    tgemm<EPI_NONE, __half><<<dim3(4, 196), 256, TGEMM_SMEM>>>(o1, wprwt, wproj_b, w2, NTOK, CC, CC, 0.f);
    merge_ln1<<<NTOK / 8, 256>>>(visual, ln1_g, ln1_b);
    tgemm<EPI_SCALE, __half><<<dim3(4, 196), 256, TGEMM_SMEM>>>(pq, caint, ca_in_b, q2, NTOK, CC, CC, 0.17677669529663687f);
    ca_attn<<<BW_ * NH_, 256>>>();
    tgemm<EPI_NONE, __half><<<dim3(4, 196), 256, TGEMM_SMEM>>>(co1, caoutt, ca_out_b, co2, NTOK, CC, CC, 0.f);
    ca_ln2<<<NTOK / 8, 256>>>(ln2_g, ln2_b);
    tgemm<EPI_GELU, __half><<<dim3(16, 196), 256, TGEMM_SMEM>>>(sk2r, ff1t, ff_b1, ffh, NTOK, 4 * CC, CC, 0.f);
    tgemm<EPI_NONE, __half><<<dim3(4, 196), 256, TGEMM_SMEM>>>(ffh, ff2t, ff_b2, ffo, NTOK, CC, 2048, 0.f);
    final_kernel<<<NTOK / 8, 256>>>(out, ln3_g, ln3_b);
}

// round 14
// speedup vs baseline: 1.0460x; 1.0460x over previous
#include <cuda_runtime.h>
#include <cuda_fp16.h>
#include <math.h>
#include <stdint.h>

// Problem constants
#define BB    8
#define CC    512
#define HH    56
#define WW_   56
#define HWSZ  3136
#define WS_   7
#define SS_   3
#define NH_   16
#define HD_   32
#define T_    49
#define NW_   64
#define BW_   512          // BB * NW_
#define NTOK  25088        // BW_ * T_
#define L_    64

// ---------------- scratch (device globals; no runtime alloc) ----------------
__device__ __align__(16) __half g_vin [512 * 256];
__device__ __align__(16) __half g_vec [BW_ * CC];
__device__ __align__(16) __half g_tok [NTOK * CC];
__device__ __align__(16) __half g_qkv [NTOK * 3 * CC];
__device__ __align__(16) __half g_o1  [NTOK * CC];
__device__ __align__(16) __half g_w2  [NTOK * CC];
__device__ float  g_skipa[NTOK * CC];       // skip1 [B,HW,C] full fp32
__device__ __align__(16) __half g_pq  [NTOK * CC];
__device__ __align__(16) __half g_q2  [NTOK * CC];
__device__ __align__(16) __half g_kv2 [BW_ * 2 * CC];   // [B*L, 1024]: k | v
__device__ __align__(16) __half g_co1 [NTOK * CC];
__device__ __align__(16) __half g_co2 [NTOK * CC];
__device__ __align__(16) __half g_skip2[NTOK * CC];     // fp16 (GEMM A + residual)
__device__ __align__(16) __half g_ffh [NTOK * 4 * CC];
__device__ __align__(16) __half g_ffo [NTOK * CC];
__device__ float  g_bias[NH_ * T_ * T_];

// transposed (fp16) weights: [N, K] K-contiguous
__device__ __align__(16) __half g_tmw_t  [512 * 256];
__device__ __align__(16) __half g_qkvw_t [1536 * 512];
__device__ __align__(16) __half g_wprw_t [512 * 512];
__device__ __align__(16) __half g_cain_t [1536 * 512];
__device__ __align__(16) __half g_caout_t[512 * 512];
__device__ __align__(16) __half g_ff1_t  [2048 * 512];
__device__ __align__(16) __half g_ff2_t  [512 * 2048];

// ---------------- helpers ----------------
__device__ __forceinline__ float gelu_exact(float x) {
    return 0.5f * x * (1.0f + erff(x * 0.70710678118654752f));
}
__device__ __forceinline__ uint32_t s2u(const void* p) {
    uint32_t a;
    asm("{ .reg .u64 t; cvta.to.shared.u64 t, %1; cvt.u32.u64 %0, t; }"
        : "=r"(a) : "l"(p));
    return a;
}

__device__ __forceinline__ void block_meanvar(float s, float ss, int n,
                                              float* mu, float* rstd) {
    #pragma unroll
    for (int o = 16; o > 0; o >>= 1) {
        s  += __shfl_down_sync(0xffffffffu, s,  o);
        ss += __shfl_down_sync(0xffffffffu, ss, o);
    }
    __shared__ float rs[8], rss[8], res[2];
    int lane = threadIdx.x & 31, wid = threadIdx.x >> 5;
    if (lane == 0) { rs[wid] = s; rss[wid] = ss; }
    __syncthreads();
    if (threadIdx.x == 0) {
        float S = 0.f, SS2 = 0.f;
        #pragma unroll
        for (int i = 0; i < 8; i++) { S += rs[i]; SS2 += rss[i]; }
        float m = S / n;
        float var = SS2 / n - m * m;
        res[0] = m; res[1] = rsqrtf(var + 1e-5f);
    }
    __syncthreads();
    *mu = res[0]; *rstd = res[1];
}

// ---------------- fp16 mma.sync GEMM (3-stage pipeline + ldmatrix) ----------
#define EPI_NONE  0
#define EPI_GELU  1
#define EPI_SCALE 2

#define LDPAD_H 40
#define TILEH (128 * LDPAD_H)            // halves per tile
#define TGEMM_SMEM (6 * TILEH * 2)       // 3 stages x (A+B), bytes = 61440

__device__ __forceinline__ void mma_f16(float* c, const uint32_t* a,
                                        const uint32_t* b) {
    asm volatile(
        "mma.sync.aligned.m16n8k16.row.col.f32.f16.f16.f32 "
        "{%0,%1,%2,%3}, {%4,%5,%6,%7}, {%8,%9}, {%0,%1,%2,%3};"
        : "+f"(c[0]), "+f"(c[1]), "+f"(c[2]), "+f"(c[3])
        : "r"(a[0]), "r"(a[1]), "r"(a[2]), "r"(a[3]),
          "r"(b[0]), "r"(b[1]));
}

#define LDSM_X4(r0, r1, r2, r3, addr) \
    asm volatile("ldmatrix.sync.aligned.m8n8.x4.shared.b16 {%0,%1,%2,%3}, [%4];" \
        : "=r"(r0), "=r"(r1), "=r"(r2), "=r"(r3) : "r"(addr))

__device__ __forceinline__ void store2(float* p, float a, float b) {
    *(float2*)p = make_float2(a, b);
}
__device__ __forceinline__ void store2(__half* p, float a, float b) {
    *(__half2*)p = __floats2half2_rn(a, b);
}

template <int EPI, typename OutT>
__global__ __launch_bounds__(256, 2)
void tgemm(const __half* __restrict__ A, const __half* __restrict__ W,
           const float* __restrict__ bias, OutT* __restrict__ C,
           int M, int N, int K, float alpha) {
    extern __shared__ __half smh[];
    __half* Abuf = smh;                  // [3][128][LDPAD_H]
    __half* Bbuf = smh + 3 * TILEH;      // [3][128][LDPAD_H]
    const uint32_t sm_a = s2u(Abuf), sm_b = s2u(Bbuf);

    const int tid = threadIdx.x;
    const int wid = tid >> 5, lane = tid & 31;
    const int m0 = blockIdx.y << 7, n0 = blockIdx.x << 7;
    const int wm = wid & 3, wn = wid >> 2;
    const int m_off = wm << 5;
    const int n_off = wn << 6;

    const __half* Abase = A + (size_t)m0 * K;
    const __half* Wbase = W + (size_t)n0 * K;
    const int NC = K >> 5;

    const int seg = tid & 3;
    const int lr0 = tid >> 2;

    auto load_chunk = [&](int c, int sel) {
        uint32_t ab = sm_a + sel * (TILEH * 2);
        uint32_t bb = sm_b + sel * (TILEH * 2);
        const __half* As = Abase + c * 32 + seg * 8;
        const __half* Ws = Wbase + c * 32 + seg * 8;
        #pragma unroll
        for (int i = 0; i < 2; i++) {
            int r = lr0 + (i << 6);
            uint32_t so = (uint32_t)(r * (LDPAD_H * 2) + seg * 16);
            asm volatile("cp.async.cg.shared.global [%0], [%1], 16;"
                         :: "r"(ab + so), "l"(As + (size_t)r * K));
            asm volatile("cp.async.cg.shared.global [%0], [%1], 16;"
                         :: "r"(bb + so), "l"(Ws + (size_t)r * K));
        }
        asm volatile("cp.async.commit_group;" ::: "memory");
    };

    const int lm = lane >> 3, lr = lane & 7;
    uint32_t a_off[2], b_off[4];
    #pragma unroll
    for (int mt = 0; mt < 2; mt++) {
        int row = m_off + mt * 16 + lr + (lm & 1) * 8;
        int koff = (lm >> 1) * 8;
        a_off[mt] = (uint32_t)((row * LDPAD_H + koff) * 2);
    }
    #pragma unroll
    for (int g = 0; g < 4; g++) {
        int row = n_off + (2 * g + (lm >> 1)) * 8 + lr;
        int koff = (lm & 1) * 8;
        b_off[g] = (uint32_t)((row * LDPAD_H + koff) * 2);
    }

    float acc[2][8][4];
    #pragma unroll
    for (int i = 0; i < 2; i++)
        #pragma unroll
        for (int j = 0; j < 8; j++)
            #pragma unroll
            for (int q = 0; q < 4; q++) acc[i][j][q] = 0.f;

    load_chunk(0, 0);
    if (NC > 1) load_chunk(1, 1);

    const int qr = lane >> 2, qc = lane & 3;
    int sel = 0;

    for (int c = 0; c < NC; c++) {
        if (c + 1 < NC)
            asm volatile("cp.async.wait_group 1;" ::: "memory");
        else
            asm volatile("cp.async.wait_group 0;" ::: "memory");
        __syncthreads();
        if (c + 2 < NC) {
            int s2 = sel + 2; if (s2 >= 3) s2 -= 3;
            load_chunk(c + 2, s2);
        }

        const uint32_t abase = sm_a + sel * (TILEH * 2);
        const uint32_t bbase = sm_b + sel * (TILEH * 2);

        #pragma unroll
        for (int ks = 0; ks < 2; ks++) {
            const uint32_t kb = ks * 32;
            uint32_t a[2][4], b[8][2];
            #pragma unroll
            for (int mt = 0; mt < 2; mt++)
                LDSM_X4(a[mt][0], a[mt][1], a[mt][2], a[mt][3],
                        abase + a_off[mt] + kb);
            #pragma unroll
            for (int g = 0; g < 4; g++)
                LDSM_X4(b[2 * g][0], b[2 * g][1], b[2 * g + 1][0], b[2 * g + 1][1],
                        bbase + b_off[g] + kb);
            #pragma unroll
            for (int mt = 0; mt < 2; mt++)
                #pragma unroll
                for (int nt = 0; nt < 8; nt++)
                    mma_f16(acc[mt][nt], a[mt], b[nt]);
        }
        if (++sel >= 3) sel = 0;
    }

    #pragma unroll
    for (int mt = 0; mt < 2; mt++) {
        #pragma unroll
        for (int half = 0; half < 2; half++) {
            int row = m0 + m_off + mt * 16 + qr + half * 8;
            OutT* Cp = C + (size_t)row * N + n0 + n_off;
            #pragma unroll
            for (int nt = 0; nt < 8; nt++) {
                int col = nt * 8 + qc * 2;
                float v0 = acc[mt][nt][half * 2 + 0] + bias[n0 + n_off + col];
                float v1 = acc[mt][nt][half * 2 + 1] + bias[n0 + n_off + col + 1];
                if (EPI == EPI_GELU)  { v0 = gelu_exact(v0); v1 = gelu_exact(v1); }
                if (EPI == EPI_SCALE) { v0 *= alpha; v1 *= alpha; }
                store2(Cp + col, v0, v1);
            }
        }
    }
}

// ---------------- batched weight transpose + fp16 ----------------
struct TWSeg { const float* src; __half* dst; int K; int N; int tile0; };
struct TWArgs { TWSeg seg[7]; int total; };

__global__ __launch_bounds__(256)
void transpose_all(TWArgs a) {
    int bid = blockIdx.x;
    int si = 0;
    #pragma unroll
    for (int i = 1; i < 7; i++)
        if (bid >= a.seg[i].tile0) si = i;
    const TWSeg sg = a.seg[si];
    int local = bid - sg.tile0;
    int tilesX = sg.N >> 5;
    int nb = (local % tilesX) << 5;
    int kb = (local / tilesX) << 5;

    __shared__ float tile[32][33];
    int tx = threadIdx.x & 31, ty = threadIdx.x >> 5;
    #pragma unroll
    for (int i = 0; i < 32; i += 8)
        tile[ty + i][tx] = sg.src[(size_t)(kb + ty + i) * sg.N + nb + tx];
    __syncthreads();
    #pragma unroll
    for (int i = 0; i < 32; i += 8)
        sg.dst[(size_t)(nb + ty + i) * sg.K + kb + tx] =
            __float2half_rn(tile[tx][ty + i]);
}

__global__ void half_copy(const float* __restrict__ in, __half* __restrict__ o, int n) {
    int i = blockIdx.x * 256 + threadIdx.x;
    if (i < n) o[i] = __float2half_rn(in[i]);
}

// ---------------- relative-position bias precompute ----------------
__global__ void bias_kernel(const float* __restrict__ w1, const float* __restrict__ b1,
                            const float* __restrict__ w2, const float* __restrict__ b2) {
    int pair = blockIdx.x;
    int q = pair / T_, k = pair % T_;
    float d0 = (float)(q / WS_ - k / WS_);
    float d1 = (float)(q % WS_ - k % WS_);
    float r0 = (d0 > 0.f ? 1.f : (d0 < 0.f ? -1.f : 0.f)) * log1pf(fabsf(d0));
    float r1 = (d1 > 0.f ? 1.f : (d1 < 0.f ? -1.f : 0.f)) * log1pf(fabsf(d1));
    int tid = threadIdx.x;
    __shared__ float hbuf[256];
    float hv = r0 * w1[tid] + r1 * w1[256 + tid] + b1[tid];
    hbuf[tid] = fmaxf(hv, 0.f);
    __syncthreads();
    if (tid < NH_) {
        float s = b2[tid];
        #pragma unroll 8
        for (int j = 0; j < 256; j++) s += hbuf[j] * w2[j * NH_ + tid];
        g_bias[tid * (T_ * T_) + pair] = s;
    }
}

// ---------------- roll(-3,-3) + unfold into token rows (fp16) ---------------
__global__ __launch_bounds__(256)
void unfold_kernel(const float* __restrict__ visual) {
    int r = blockIdx.x;
    int bw = r / T_, t = r % T_;
    int b = bw / NW_, win = bw % NW_, wh = win >> 3, ww = win & 7;
    int h = (wh * WS_ + t / WS_ + SS_) % HH;
    int w = (ww * WS_ + t % WS_ + SS_) % WW_;
    int hw = h * WW_ + w;
    for (int c = threadIdx.x; c < CC; c += 256)
        g_tok[(size_t)r * CC + c] = __float2half_rn(visual[(size_t)(b * CC + c) * HWSZ + hw]);
}

// ---------------- window attention (register-blocked) ----------------
#define SQS 36   // padded row stride (floats)
__global__ __launch_bounds__(256)
void win_attn(const float* __restrict__ tau) {
    int bw = blockIdx.x >> 4;
    int hh = blockIdx.x & 15;
    int tid = threadIdx.x;

    __shared__ __align__(16) float sq[52 * SQS], sk[52 * SQS], sv[52 * SQS];
    __shared__ float ss[50 * 50];
    __shared__ float nq[52], nk[52];
    __shared__ int   rg[T_];

    for (int i = tid; i < 3 * 32; i += 256) {
        int r = 49 + i / 32, c = i % 32;
        sq[r * SQS + c] = 0.f; sk[r * SQS + c] = 0.f; sv[r * SQS + c] = 0.f;
    }

    size_t base = (size_t)(bw * T_) * (3 * CC);
    for (int idx = tid; idx < T_ * HD_; idx += 256) {
        int t = idx / HD_, d = idx % HD_;
        size_t ro = base + (size_t)t * (3 * CC) + hh * HD_ + d;
        sq[t * SQS + d] = __half2float(g_qkv[ro]);
        sk[t * SQS + d] = __half2float(g_qkv[ro + CC]);
        sv[t * SQS + d] = __half2float(g_qkv[ro + 2 * CC]);
    }
    int win = bw & 63, wh = win >> 3, ww = win & 7;
    if (tid < T_) {
        int row = wh * WS_ + tid / WS_;
        int col = ww * WS_ + tid % WS_;
        int rh = row < 49 ? 0 : (row < 53 ? 1 : 2);
        int rw = col < 49 ? 0 : (col < 53 ? 1 : 2);
        rg[tid] = rh * 3 + rw;
    }
    __syncthreads();

    if (tid < 52) {
        if (tid < T_) {
            float s1 = 0.f, s2 = 0.f;
            #pragma unroll
            for (int d = 0; d < HD_; d++) {
                float a = sq[tid * SQS + d], b = sk[tid * SQS + d];
                s1 += a * a; s2 += b * b;
            }
            nq[tid] = sqrtf(s1); nk[tid] = sqrtf(s2);
        } else {
            nq[tid] = 1.f; nk[tid] = 1.f;
        }
    }
    __syncthreads();

    float tauh = fmaxf(tau[hh], 0.01f);
    const float* bh = &g_bias[hh * (T_ * T_)];
    if (tid < 169) {
        int q0 = (tid / 13) * 4, k0 = (tid % 13) * 4;
        float acc[4][4];
        #pragma unroll
        for (int i = 0; i < 4; i++)
            #pragma unroll
            for (int j = 0; j < 4; j++) acc[i][j] = 0.f;
        #pragma unroll
        for (int d4 = 0; d4 < 8; d4++) {
            float4 qv[4], kv[4];
            #pragma unroll
            for (int i = 0; i < 4; i++)
                qv[i] = *(const float4*)&sq[(q0 + i) * SQS + d4 * 4];
            #pragma unroll
            for (int j = 0; j < 4; j++)
                kv[j] = *(const float4*)&sk[(k0 + j) * SQS + d4 * 4];
            #pragma unroll
            for (int i = 0; i < 4; i++)
                #pragma unroll
                for (int j = 0; j < 4; j++)
                    acc[i][j] += qv[i].x * kv[j].x + qv[i].y * kv[j].y
                               + qv[i].z * kv[j].z + qv[i].w * kv[j].w;
        }
        #pragma unroll
        for (int i = 0; i < 4; i++) {
            int q = q0 + i;
            if (q >= T_) break;
            #pragma unroll
            for (int j = 0; j < 4; j++) {
                int k = k0 + j;
                if (k >= T_) continue;
                float s = acc[i][j] / fmaxf(nq[q] * nk[k], 1e-6f) / tauh
                        + bh[q * T_ + k];
                if (rg[q] != rg[k]) s -= 100.0f;
                ss[q * 50 + k] = s;
            }
        }
    }
    __syncthreads();

    if (tid < T_) {
        float m = -1e30f;
        for (int k = 0; k < T_; k++) m = fmaxf(m, ss[tid * 50 + k]);
        float sum = 0.f;
        for (int k = 0; k < T_; k++) {
            float e = expf(ss[tid * 50 + k] - m);
            ss[tid * 50 + k] = e; sum += e;
        }
        float inv = 1.f / sum;
        for (int k = 0; k < T_; k++) ss[tid * 50 + k] *= inv;
    }
    __syncthreads();

    if (tid < 200) {
        int t0 = (tid / 8) * 2, d4 = tid % 8;
        float4 a0 = make_float4(0.f, 0.f, 0.f, 0.f), a1 = a0;
        for (int k = 0; k < T_; k++) {
            float s0 = ss[t0 * 50 + k];
            float s1 = ss[(t0 + 1) * 50 + k];
            float4 v = *(const float4*)&sv[k * SQS + d4 * 4];
            a0.x += s0 * v.x; a0.y += s0 * v.y; a0.z += s0 * v.z; a0.w += s0 * v.w;
            a1.x += s1 * v.x; a1.y += s1 * v.y; a1.z += s1 * v.z; a1.w += s1 * v.w;
        }
        __half* op = g_o1 + (size_t)(bw * T_ + t0) * CC + hh * HD_ + d4 * 4;
        ((__half2*)op)[0] = __floats2half2_rn(a0.x, a0.y);
        ((__half2*)op)[1] = __floats2half2_rn(a0.z, a0.w);
        if (t0 + 1 < T_) {
            __half* op1 = op + CC;
            ((__half2*)op1)[0] = __floats2half2_rn(a1.x, a1.y);
            ((__half2*)op1)[1] = __floats2half2_rn(a1.z, a1.w);
        }
    }
}

// ---------------- fold+roll(+3) + LN1 + residual; emit CA query tokens ------
__global__ __launch_bounds__(256)
void merge_ln1(const float* __restrict__ visual,
               const float* __restrict__ g, const float* __restrict__ bt) {
    int pos = blockIdx.x;
    int b = pos / HWSZ, hw = pos % HWSZ;
    int h = hw / WW_, w = hw % WW_;
    int hp = (h + HH - SS_) % HH, wp = (w + WW_ - SS_) % WW_;
    int rm = (b * NW_ + (hp / WS_) * 8 + (wp / WS_)) * T_ + (hp % WS_) * WS_ + (wp % WS_);

    __shared__ float x[CC];
    int tid = threadIdx.x;
    float s = 0.f, ss2 = 0.f;
    for (int c = tid; c < CC; c += 256) {
        float v = __half2float(g_w2[(size_t)rm * CC + c]);
        x[c] = v; s += v; ss2 += v * v;
    }
    float mu, rstd;
    block_meanvar(s, ss2, CC, &mu, &rstd);
    for (int c = tid; c < CC; c += 256) {
        float v = (x[c] - mu) * rstd * g[c] + bt[c]
                + visual[(size_t)(b * CC + c) * HWSZ + hw];
        g_skipa[(size_t)pos * CC + c] = v;
        g_pq  [(size_t)rm  * CC + c] = __float2half_rn(v);
    }
}

// ---------------- cross attention (register-blocked) ----------------
__global__ __launch_bounds__(256)
void ca_attn() {
    int bw = blockIdx.x >> 4;
    int hh = blockIdx.x & 15;
    int bkv = bw & 7;
    int tid = threadIdx.x;

    __shared__ __align__(16) float sq[52 * SQS], sk[L_ * SQS], sv[L_ * SQS];
    __shared__ float ss[50 * 65];

    for (int i = tid; i < 3 * 32; i += 256) {
        int r = 49 + i / 32, c = i % 32;
        sq[r * SQS + c] = 0.f;
    }
    for (int idx = tid; idx < T_ * HD_; idx += 256) {
        int t = idx / HD_, d = idx % HD_;
        sq[t * SQS + d] = __half2float(g_q2[(size_t)(bw * T_ + t) * CC + hh * HD_ + d]);
    }
    for (int idx = tid; idx < L_ * HD_; idx += 256) {
        int l = idx / HD_, d = idx % HD_;
        size_t ro = (size_t)(bkv * L_ + l) * (2 * CC) + hh * HD_ + d;
        sk[l * SQS + d] = __half2float(g_kv2[ro]);
        sv[l * SQS + d] = __half2float(g_kv2[ro + CC]);
    }
    __syncthreads();

    if (tid < 208) {
        int q0 = (tid / 16) * 4, l0 = (tid % 16) * 4;
        float acc[4][4];
        #pragma unroll
        for (int i = 0; i < 4; i++)
            #pragma unroll
            for (int j = 0; j < 4; j++) acc[i][j] = 0.f;
        #pragma unroll
        for (int d4 = 0; d4 < 8; d4++) {
            float4 qv[4], kv[4];
            #pragma unroll
            for (int i = 0; i < 4; i++)
                qv[i] = *(const float4*)&sq[(q0 + i) * SQS + d4 * 4];
            #pragma unroll
            for (int j = 0; j < 4; j++)
                kv[j] = *(const float4*)&sk[(l0 + j) * SQS + d4 * 4];
            #pragma unroll
            for (int i = 0; i < 4; i++)
                #pragma unroll
                for (int j = 0; j < 4; j++)
                    acc[i][j] += qv[i].x * kv[j].x + qv[i].y * kv[j].y
                               + qv[i].z * kv[j].z + qv[i].w * kv[j].w;
        }
        #pragma unroll
        for (int i = 0; i < 4; i++) {
            int q = q0 + i;
            if (q >= T_) break;
            #pragma unroll
            for (int j = 0; j < 4; j++)
                ss[q * 65 + l0 + j] = acc[i][j];
        }
    }
    __syncthreads();

    if (tid < T_) {
        float m = -1e30f;
        for (int l = 0; l < L_; l++) m = fmaxf(m, ss[tid * 65 + l]);
        float sum = 0.f;
        for (int l = 0; l < L_; l++) {
            float e = expf(ss[tid * 65 + l] - m);
            ss[tid * 65 + l] = e; sum += e;
        }
        float inv = 1.f / sum;
        for (int l = 0; l < L_; l++) ss[tid * 65 + l] *= inv;
    }
    __syncthreads();

    if (tid < 200) {
        int t0 = (tid / 8) * 2, d4 = tid % 8;
        float4 a0 = make_float4(0.f, 0.f, 0.f, 0.f), a1 = a0;
        for (int l = 0; l < L_; l++) {
            float s0 = ss[t0 * 65 + l];
            float s1 = ss[(t0 + 1) * 65 + l];
            float4 v = *(const float4*)&sv[l * SQS + d4 * 4];
            a0.x += s0 * v.x; a0.y += s0 * v.y; a0.z += s0 * v.z; a0.w += s0 * v.w;
            a1.x += s1 * v.x; a1.y += s1 * v.y; a1.z += s1 * v.z; a1.w += s1 * v.w;
        }
        __half* op = g_co1 + (size_t)(bw * T_ + t0) * CC + hh * HD_ + d4 * 4;
        ((__half2*)op)[0] = __floats2half2_rn(a0.x, a0.y);
        ((__half2*)op)[1] = __floats2half2_rn(a0.z, a0.w);
        if (t0 + 1 < T_) {
            __half* op1 = op + CC;
            ((__half2*)op1)[0] = __floats2half2_rn(a1.x, a1.y);
            ((__half2*)op1)[1] = __floats2half2_rn(a1.z, a1.w);
        }
    }
}

// ---------------- LN2 + fold+roll(+3) + residual ----------------
__global__ __launch_bounds__(256)
void ca_ln2(const float* __restrict__ g, const float* __restrict__ bt) {
    int r = blockIdx.x;
    int bw = r / T_, t = r % T_;
    int b = bw / NW_, win = bw % NW_, wh = win >> 3, ww = win & 7;
    int h = (wh * WS_ + t / WS_ + SS_) % HH;
    int w = (ww * WS_ + t % WS_ + SS_) % WW_;
    int pos = b * HWSZ + h * WW_ + w;

    __shared__ float x[CC];
    int tid = threadIdx.x;
    float s = 0.f, ss2 = 0.f;
    for (int c = tid; c < CC; c += 256) {
        float v = __half2float(g_co2[(size_t)r * CC + c]);
        x[c] = v; s += v; ss2 += v * v;
    }
    float mu, rstd;
    block_meanvar(s, ss2, CC, &mu, &rstd);
    for (int c = tid; c < CC; c += 256) {
        float v = (x[c] - mu) * rstd * g[c] + bt[c]
                + g_skipa[(size_t)pos * CC + c];
        g_skip2[(size_t)pos * CC + c] = __float2half_rn(v);
    }
}

// ---------------- LN3(ff) + skip2, write [B,C,H,W] ----------------
__global__ __launch_bounds__(256)
void final_kernel(float* __restrict__ out,
                  const float* __restrict__ g, const float* __restrict__ bt) {
    int pos = blockIdx.x;
    int b = pos / HWSZ, hw = pos % HWSZ;

    __shared__ float x[CC];
    int tid = threadIdx.x;
    float s = 0.f, ss2 = 0.f;
    for (int c = tid; c < CC; c += 256) {
        float v = __half2float(g_ffo[(size_t)pos * CC + c]);
        x[c] = v; s += v; ss2 += v * v;
    }
    float mu, rstd;
    block_meanvar(s, ss2, CC, &mu, &rstd);
    for (int c = tid; c < CC; c += 256) {
        float v = (x[c] - mu) * rstd * g[c] + bt[c];
        out[(size_t)(b * CC + c) * HWSZ + hw] =
            __half2float(g_skip2[(size_t)pos * CC + c]) + v;
    }
}

// ---------------- launch ----------------
extern "C" void kernel_launch(void* const* d_in, const int* in_sizes, int n_in,
                              void* d_out, int out_size) {
    const float* visual   = (const float*)d_in[0];
    const float* vector   = (const float*)d_in[1];
    const float* tm_w     = (const float*)d_in[2];
    const float* tm_b     = (const float*)d_in[3];
    const float* ln1_g    = (const float*)d_in[4];
    const float* ln1_b    = (const float*)d_in[5];
    const float* ln2_g    = (const float*)d_in[6];
    const float* ln2_b    = (const float*)d_in[7];
    const float* ln3_g    = (const float*)d_in[8];
    const float* ln3_b    = (const float*)d_in[9];
    const float* qkv_w    = (const float*)d_in[10];
    const float* qkv_b    = (const float*)d_in[11];
    const float* wproj_w  = (const float*)d_in[12];
    const float* wproj_b  = (const float*)d_in[13];
    const float* meta_w1  = (const float*)d_in[14];
    const float* meta_b1  = (const float*)d_in[15];
    const float* meta_w2  = (const float*)d_in[16];
    const float* meta_b2  = (const float*)d_in[17];
    const float* tau      = (const float*)d_in[18];
    const float* ca_in_w  = (const float*)d_in[19];
    const float* ca_in_b  = (const float*)d_in[20];
    const float* ca_out_w = (const float*)d_in[21];
    const float* ca_out_b = (const float*)d_in[22];
    const float* ff_w1    = (const float*)d_in[23];
    const float* ff_b1    = (const float*)d_in[24];
    const float* ff_w2    = (const float*)d_in[25];
    const float* ff_b2    = (const float*)d_in[26];
    float* out = (float*)d_out;

    __half *vin, *vec, *tok, *o1, *pq, *co1, *sk2, *ffh;
    __half *qkv, *w2, *q2, *kv2, *co2, *ffo;
    __half *tmwt, *qkvwt, *wprwt, *caint, *caoutt, *ff1t, *ff2t;
    cudaGetSymbolAddress((void**)&vin,   g_vin);
    cudaGetSymbolAddress((void**)&vec,   g_vec);
    cudaGetSymbolAddress((void**)&tok,   g_tok);
    cudaGetSymbolAddress((void**)&qkv,   g_qkv);
    cudaGetSymbolAddress((void**)&o1,    g_o1);
    cudaGetSymbolAddress((void**)&w2,    g_w2);
    cudaGetSymbolAddress((void**)&pq,    g_pq);
    cudaGetSymbolAddress((void**)&q2,    g_q2);
    cudaGetSymbolAddress((void**)&kv2,   g_kv2);
    cudaGetSymbolAddress((void**)&co1,   g_co1);
    cudaGetSymbolAddress((void**)&co2,   g_co2);
    cudaGetSymbolAddress((void**)&sk2,   g_skip2);
    cudaGetSymbolAddress((void**)&ffh,   g_ffh);
    cudaGetSymbolAddress((void**)&ffo,   g_ffo);
    cudaGetSymbolAddress((void**)&tmwt,  g_tmw_t);
    cudaGetSymbolAddress((void**)&qkvwt, g_qkvw_t);
    cudaGetSymbolAddress((void**)&wprwt, g_wprw_t);
    cudaGetSymbolAddress((void**)&caint, g_cain_t);
    cudaGetSymbolAddress((void**)&caoutt,g_caout_t);
    cudaGetSymbolAddress((void**)&ff1t,  g_ff1_t);
    cudaGetSymbolAddress((void**)&ff2t,  g_ff2_t);

    cudaFuncSetAttribute((const void*)tgemm<EPI_NONE,  __half>, cudaFuncAttributeMaxDynamicSharedMemorySize, TGEMM_SMEM);
    cudaFuncSetAttribute((const void*)tgemm<EPI_GELU,  __half>, cudaFuncAttributeMaxDynamicSharedMemorySize, TGEMM_SMEM);
    cudaFuncSetAttribute((const void*)tgemm<EPI_SCALE, __half>, cudaFuncAttributeMaxDynamicSharedMemorySize, TGEMM_SMEM);

    // batched weight transposes (+fp16 rounding); tile counts:
    // tm 128, qkv 768, wproj 256, cain 768, caout 256, ff1 1024, ff2 1024
    TWArgs twa;
    twa.seg[0] = { tm_w,     tmwt,   256,  512,    0 };
    twa.seg[1] = { qkv_w,    qkvwt,  512, 1536,  128 };
    twa.seg[2] = { wproj_w,  wprwt,  512,  512,  896 };
    twa.seg[3] = { ca_in_w,  caint,  512, 1536, 1152 };
    twa.seg[4] = { ca_out_w, caoutt, 512,  512, 1920 };
    twa.seg[5] = { ff_w1,    ff1t,   512, 2048, 2176 };
    twa.seg[6] = { ff_w2,    ff2t,  2048,  512, 3200 };
    twa.total = 4224;
    transpose_all<<<4224, 256>>>(twa);
    half_copy<<<512, 256>>>(vector, vin, 512 * 256);

    bias_kernel<<<T_ * T_, 256>>>(meta_w1, meta_b1, meta_w2, meta_b2);

    // vec = gelu(vector @ tm_w + tm_b)
    tgemm<EPI_GELU, __half><<<dim3(4, 4), 256, TGEMM_SMEM>>>(vin, tmwt, tm_b, vec, 512, 512, 256, 0.f);
    // K2|V2 fused
    tgemm<EPI_NONE, __half><<<dim3(8, 4), 256, TGEMM_SMEM>>>(vec, caint + 512 * 512, ca_in_b + 512, kv2, 512, 1024, 512, 0.f);

    unfold_kernel<<<NTOK, 256>>>(visual);
    tgemm<EPI_NONE, __half><<<dim3(12, 196), 256, TGEMM_SMEM>>>(tok, qkvwt, qkv_b, qkv, NTOK, 3 * CC, CC, 0.f);
    win_attn<<<BW_ * NH_, 256>>>(tau);
    tgemm<EPI_NONE, __half><<<dim3(4, 196), 256, TGEMM_SMEM>>>(o1, wprwt, wproj_b, w2, NTOK, CC, CC, 0.f);
    merge_ln1<<<BB * HWSZ, 256>>>(visual, ln1_g, ln1_b);
    tgemm<EPI_SCALE, __half><<<dim3(4, 196), 256, TGEMM_SMEM>>>(pq, caint, ca_in_b, q2, NTOK, CC, CC, 0.17677669529663687f);
    ca_attn<<<BW_ * NH_, 256>>>();
    tgemm<EPI_NONE, __half><<<dim3(4, 196), 256, TGEMM_SMEM>>>(co1, caoutt, ca_out_b, co2, NTOK, CC, CC, 0.f);
    ca_ln2<<<NTOK, 256>>>(ln2_g, ln2_b);
    tgemm<EPI_GELU, __half><<<dim3(16, 196), 256, TGEMM_SMEM>>>(sk2, ff1t, ff_b1, ffh, NTOK, 4 * CC, CC, 0.f);
    tgemm<EPI_NONE, __half><<<dim3(4, 196), 256, TGEMM_SMEM>>>(ffh, ff2t, ff_b2, ffo, NTOK, CC, 2048, 0.f);
    final_kernel<<<BB * HWSZ, 256>>>(out, ln3_g, ln3_b);
}

// round 15
// speedup vs baseline: 1.0737x; 1.0265x over previous
#include <cuda_runtime.h>
#include <cuda_fp16.h>
#include <math.h>
#include <stdint.h>

// Problem constants
#define BB    8
#define CC    512
#define HH    56
#define WW_   56
#define HWSZ  3136
#define WS_   7
#define SS_   3
#define NH_   16
#define HD_   32
#define T_    49
#define NW_   64
#define BW_   512          // BB * NW_
#define NTOK  25088        // BW_ * T_
#define L_    64

// ---------------- scratch (device globals; no runtime alloc) ----------------
__device__ __align__(16) __half g_vin [512 * 256];
__device__ __align__(16) __half g_vec [BW_ * CC];
__device__ __align__(16) __half g_tok [NTOK * CC];
__device__ __align__(16) __half g_qkv [NTOK * 3 * CC];
__device__ __align__(16) __half g_o1  [NTOK * CC];
__device__ __align__(16) __half g_w2  [NTOK * CC];
__device__ __align__(16) __half g_skipa[NTOK * CC];     // skip1 fp16
__device__ __align__(16) __half g_pq  [NTOK * CC];
__device__ __align__(16) __half g_q2  [NTOK * CC];
__device__ __align__(16) __half g_kv2 [BW_ * 2 * CC];   // [B*L, 1024]: k | v
__device__ __align__(16) __half g_co1 [NTOK * CC];
__device__ __align__(16) __half g_co2 [NTOK * CC];
__device__ __align__(16) __half g_skip2[NTOK * CC];     // fp16 (GEMM A + residual)
__device__ __align__(16) __half g_ffh [NTOK * 4 * CC];
__device__ __align__(16) __half g_ffo [NTOK * CC];
__device__ float  g_bias[NH_ * T_ * T_];

// transposed (fp16) weights: [N, K] K-contiguous
__device__ __align__(16) __half g_tmw_t  [512 * 256];
__device__ __align__(16) __half g_qkvw_t [1536 * 512];
__device__ __align__(16) __half g_wprw_t [512 * 512];
__device__ __align__(16) __half g_cain_t [1536 * 512];
__device__ __align__(16) __half g_caout_t[512 * 512];
__device__ __align__(16) __half g_ff1_t  [2048 * 512];
__device__ __align__(16) __half g_ff2_t  [512 * 2048];

// ---------------- helpers ----------------
__device__ __forceinline__ float gelu_exact(float x) {
    return 0.5f * x * (1.0f + erff(x * 0.70710678118654752f));
}
__device__ __forceinline__ uint32_t s2u(const void* p) {
    uint32_t a;
    asm("{ .reg .u64 t; cvta.to.shared.u64 t, %1; cvt.u32.u64 %0, t; }"
        : "=r"(a) : "l"(p));
    return a;
}

__device__ __forceinline__ void block_meanvar(float s, float ss, int n,
                                              float* mu, float* rstd) {
    #pragma unroll
    for (int o = 16; o > 0; o >>= 1) {
        s  += __shfl_down_sync(0xffffffffu, s,  o);
        ss += __shfl_down_sync(0xffffffffu, ss, o);
    }
    __shared__ float rs[8], rss[8], res[2];
    int lane = threadIdx.x & 31, wid = threadIdx.x >> 5;
    if (lane == 0) { rs[wid] = s; rss[wid] = ss; }
    __syncthreads();
    if (threadIdx.x == 0) {
        float S = 0.f, SS2 = 0.f;
        #pragma unroll
        for (int i = 0; i < 8; i++) { S += rs[i]; SS2 += rss[i]; }
        float m = S / n;
        float var = SS2 / n - m * m;
        res[0] = m; res[1] = rsqrtf(var + 1e-5f);
    }
    __syncthreads();
    *mu = res[0]; *rstd = res[1];
}

__device__ __forceinline__ void warp_meanvar(float s, float ss, int n,
                                             float* mu, float* rstd) {
    #pragma unroll
    for (int o = 16; o > 0; o >>= 1) {
        s  += __shfl_xor_sync(0xffffffffu, s,  o);
        ss += __shfl_xor_sync(0xffffffffu, ss, o);
    }
    float m = s / n;
    *mu = m;
    *rstd = rsqrtf(ss / n - m * m + 1e-5f);
}

// load 8 fp16 (16B) -> 8 floats
__device__ __forceinline__ void h8_to_f(const __half* src, float* dst) {
    uint4 u = *(const uint4*)src;
    const __half2* h = (const __half2*)&u;
    #pragma unroll
    for (int i = 0; i < 4; i++) {
        float2 f = __half22float2(h[i]);
        dst[2 * i] = f.x; dst[2 * i + 1] = f.y;
    }
}

// ---------------- fp16 mma.sync GEMM (3-stage pipeline + ldmatrix) ----------
#define EPI_NONE  0
#define EPI_GELU  1
#define EPI_SCALE 2

#define LDPAD_H 40
#define TILEH (128 * LDPAD_H)            // halves per tile
#define TGEMM_SMEM (6 * TILEH * 2)       // 3 stages x (A+B), bytes = 61440

__device__ __forceinline__ void mma_f16(float* c, const uint32_t* a,
                                        const uint32_t* b) {
    asm volatile(
        "mma.sync.aligned.m16n8k16.row.col.f32.f16.f16.f32 "
        "{%0,%1,%2,%3}, {%4,%5,%6,%7}, {%8,%9}, {%0,%1,%2,%3};"
        : "+f"(c[0]), "+f"(c[1]), "+f"(c[2]), "+f"(c[3])
        : "r"(a[0]), "r"(a[1]), "r"(a[2]), "r"(a[3]),
          "r"(b[0]), "r"(b[1]));
}

#define LDSM_X4(r0, r1, r2, r3, addr) \
    asm volatile("ldmatrix.sync.aligned.m8n8.x4.shared.b16 {%0,%1,%2,%3}, [%4];" \
        : "=r"(r0), "=r"(r1), "=r"(r2), "=r"(r3) : "r"(addr))

__device__ __forceinline__ void store2(float* p, float a, float b) {
    *(float2*)p = make_float2(a, b);
}
__device__ __forceinline__ void store2(__half* p, float a, float b) {
    *(__half2*)p = __floats2half2_rn(a, b);
}

template <int EPI, typename OutT>
__global__ __launch_bounds__(256, 2)
void tgemm(const __half* __restrict__ A, const __half* __restrict__ W,
           const float* __restrict__ bias, OutT* __restrict__ C,
           int M, int N, int K, float alpha) {
    extern __shared__ __half smh[];
    __half* Abuf = smh;                  // [3][128][LDPAD_H]
    __half* Bbuf = smh + 3 * TILEH;      // [3][128][LDPAD_H]
    const uint32_t sm_a = s2u(Abuf), sm_b = s2u(Bbuf);

    const int tid = threadIdx.x;
    const int wid = tid >> 5, lane = tid & 31;
    const int m0 = blockIdx.y << 7, n0 = blockIdx.x << 7;
    const int wm = wid & 3, wn = wid >> 2;
    const int m_off = wm << 5;
    const int n_off = wn << 6;

    const __half* Abase = A + (size_t)m0 * K;
    const __half* Wbase = W + (size_t)n0 * K;
    const int NC = K >> 5;

    const int seg = tid & 3;
    const int lr0 = tid >> 2;

    auto load_chunk = [&](int c, int sel) {
        uint32_t ab = sm_a + sel * (TILEH * 2);
        uint32_t bb = sm_b + sel * (TILEH * 2);
        const __half* As = Abase + c * 32 + seg * 8;
        const __half* Ws = Wbase + c * 32 + seg * 8;
        #pragma unroll
        for (int i = 0; i < 2; i++) {
            int r = lr0 + (i << 6);
            uint32_t so = (uint32_t)(r * (LDPAD_H * 2) + seg * 16);
            asm volatile("cp.async.cg.shared.global [%0], [%1], 16;"
                         :: "r"(ab + so), "l"(As + (size_t)r * K));
            asm volatile("cp.async.cg.shared.global [%0], [%1], 16;"
                         :: "r"(bb + so), "l"(Ws + (size_t)r * K));
        }
        asm volatile("cp.async.commit_group;" ::: "memory");
    };

    const int lm = lane >> 3, lr = lane & 7;
    uint32_t a_off[2], b_off[4];
    #pragma unroll
    for (int mt = 0; mt < 2; mt++) {
        int row = m_off + mt * 16 + lr + (lm & 1) * 8;
        int koff = (lm >> 1) * 8;
        a_off[mt] = (uint32_t)((row * LDPAD_H + koff) * 2);
    }
    #pragma unroll
    for (int g = 0; g < 4; g++) {
        int row = n_off + (2 * g + (lm >> 1)) * 8 + lr;
        int koff = (lm & 1) * 8;
        b_off[g] = (uint32_t)((row * LDPAD_H + koff) * 2);
    }

    float acc[2][8][4];
    #pragma unroll
    for (int i = 0; i < 2; i++)
        #pragma unroll
        for (int j = 0; j < 8; j++)
            #pragma unroll
            for (int q = 0; q < 4; q++) acc[i][j][q] = 0.f;

    load_chunk(0, 0);
    if (NC > 1) load_chunk(1, 1);

    const int qr = lane >> 2, qc = lane & 3;
    int sel = 0;

    for (int c = 0; c < NC; c++) {
        if (c + 1 < NC)
            asm volatile("cp.async.wait_group 1;" ::: "memory");
        else
            asm volatile("cp.async.wait_group 0;" ::: "memory");
        __syncthreads();
        if (c + 2 < NC) {
            int s2 = sel + 2; if (s2 >= 3) s2 -= 3;
            load_chunk(c + 2, s2);
        }

        const uint32_t abase = sm_a + sel * (TILEH * 2);
        const uint32_t bbase = sm_b + sel * (TILEH * 2);

        #pragma unroll
        for (int ks = 0; ks < 2; ks++) {
            const uint32_t kb = ks * 32;
            uint32_t a[2][4], b[8][2];
            #pragma unroll
            for (int mt = 0; mt < 2; mt++)
                LDSM_X4(a[mt][0], a[mt][1], a[mt][2], a[mt][3],
                        abase + a_off[mt] + kb);
            #pragma unroll
            for (int g = 0; g < 4; g++)
                LDSM_X4(b[2 * g][0], b[2 * g][1], b[2 * g + 1][0], b[2 * g + 1][1],
                        bbase + b_off[g] + kb);
            #pragma unroll
            for (int mt = 0; mt < 2; mt++)
                #pragma unroll
                for (int nt = 0; nt < 8; nt++)
                    mma_f16(acc[mt][nt], a[mt], b[nt]);
        }
        if (++sel >= 3) sel = 0;
    }

    #pragma unroll
    for (int mt = 0; mt < 2; mt++) {
        #pragma unroll
        for (int half = 0; half < 2; half++) {
            int row = m0 + m_off + mt * 16 + qr + half * 8;
            OutT* Cp = C + (size_t)row * N + n0 + n_off;
            #pragma unroll
            for (int nt = 0; nt < 8; nt++) {
                int col = nt * 8 + qc * 2;
                float v0 = acc[mt][nt][half * 2 + 0] + bias[n0 + n_off + col];
                float v1 = acc[mt][nt][half * 2 + 1] + bias[n0 + n_off + col + 1];
                if (EPI == EPI_GELU)  { v0 = gelu_exact(v0); v1 = gelu_exact(v1); }
                if (EPI == EPI_SCALE) { v0 *= alpha; v1 *= alpha; }
                store2(Cp + col, v0, v1);
            }
        }
    }
}

// ---------------- batched weight transpose + fp16 ----------------
struct TWSeg { const float* src; __half* dst; int K; int N; int tile0; };
struct TWArgs { TWSeg seg[7]; int total; };

__global__ __launch_bounds__(256)
void transpose_all(TWArgs a) {
    int bid = blockIdx.x;
    int si = 0;
    #pragma unroll
    for (int i = 1; i < 7; i++)
        if (bid >= a.seg[i].tile0) si = i;
    const TWSeg sg = a.seg[si];
    int local = bid - sg.tile0;
    int tilesX = sg.N >> 5;
    int nb = (local % tilesX) << 5;
    int kb = (local / tilesX) << 5;

    __shared__ float tile[32][33];
    int tx = threadIdx.x & 31, ty = threadIdx.x >> 5;
    #pragma unroll
    for (int i = 0; i < 32; i += 8)
        tile[ty + i][tx] = sg.src[(size_t)(kb + ty + i) * sg.N + nb + tx];
    __syncthreads();
    #pragma unroll
    for (int i = 0; i < 32; i += 8)
        sg.dst[(size_t)(nb + ty + i) * sg.K + kb + tx] =
            __float2half_rn(tile[tx][ty + i]);
}

__global__ void half_copy(const float* __restrict__ in, __half* __restrict__ o, int n) {
    int i = blockIdx.x * 256 + threadIdx.x;
    if (i < n) o[i] = __float2half_rn(in[i]);
}

// ---------------- relative-position bias precompute ----------------
__global__ void bias_kernel(const float* __restrict__ w1, const float* __restrict__ b1,
                            const float* __restrict__ w2, const float* __restrict__ b2) {
    int pair = blockIdx.x;
    int q = pair / T_, k = pair % T_;
    float d0 = (float)(q / WS_ - k / WS_);
    float d1 = (float)(q % WS_ - k % WS_);
    float r0 = (d0 > 0.f ? 1.f : (d0 < 0.f ? -1.f : 0.f)) * log1pf(fabsf(d0));
    float r1 = (d1 > 0.f ? 1.f : (d1 < 0.f ? -1.f : 0.f)) * log1pf(fabsf(d1));
    int tid = threadIdx.x;
    __shared__ float hbuf[256];
    float hv = r0 * w1[tid] + r1 * w1[256 + tid] + b1[tid];
    hbuf[tid] = fmaxf(hv, 0.f);
    __syncthreads();
    if (tid < NH_) {
        float s = b2[tid];
        #pragma unroll 8
        for (int j = 0; j < 256; j++) s += hbuf[j] * w2[j * NH_ + tid];
        g_bias[tid * (T_ * T_) + pair] = s;
    }
}

// ---------------- roll(-3,-3) + unfold into token rows (fp16) ---------------
__global__ __launch_bounds__(256)
void unfold_kernel(const float* __restrict__ visual) {
    int r = blockIdx.x;
    int bw = r / T_, t = r % T_;
    int b = bw / NW_, win = bw % NW_, wh = win >> 3, ww = win & 7;
    int h = (wh * WS_ + t / WS_ + SS_) % HH;
    int w = (ww * WS_ + t % WS_ + SS_) % WW_;
    int hw = h * WW_ + w;
    for (int c = threadIdx.x; c < CC; c += 256)
        g_tok[(size_t)r * CC + c] = __float2half_rn(visual[(size_t)(b * CC + c) * HWSZ + hw]);
}

// ---------------- window attention (register-blocked, vector loads) ---------
#define SQS 36   // padded row stride (floats)
__global__ __launch_bounds__(256)
void win_attn(const float* __restrict__ tau) {
    int bw = blockIdx.x >> 4;
    int hh = blockIdx.x & 15;
    int tid = threadIdx.x;

    __shared__ __align__(16) float sq[52 * SQS], sk[52 * SQS], sv[52 * SQS];
    __shared__ float ss[50 * 50];
    __shared__ float nq[52], nk[52];
    __shared__ int   rg[T_];

    for (int i = tid; i < 3 * 32; i += 256) {
        int r = 49 + i / 32, c = i % 32;
        sq[r * SQS + c] = 0.f; sk[r * SQS + c] = 0.f; sv[r * SQS + c] = 0.f;
    }

    if (tid < T_ * 4) {
        int t = tid >> 2, sg = tid & 3;
        size_t ro = (size_t)(bw * T_ + t) * (3 * CC) + hh * HD_ + sg * 8;
        h8_to_f(g_qkv + ro,           &sq[t * SQS + sg * 8]);
        h8_to_f(g_qkv + ro + CC,      &sk[t * SQS + sg * 8]);
        h8_to_f(g_qkv + ro + 2 * CC,  &sv[t * SQS + sg * 8]);
    }
    int win = bw & 63, wh = win >> 3, ww = win & 7;
    if (tid < T_) {
        int row = wh * WS_ + tid / WS_;
        int col = ww * WS_ + tid % WS_;
        int rh = row < 49 ? 0 : (row < 53 ? 1 : 2);
        int rw = col < 49 ? 0 : (col < 53 ? 1 : 2);
        rg[tid] = rh * 3 + rw;
    }
    __syncthreads();

    if (tid < 52) {
        if (tid < T_) {
            float s1 = 0.f, s2 = 0.f;
            #pragma unroll
            for (int d = 0; d < HD_; d++) {
                float a = sq[tid * SQS + d], b = sk[tid * SQS + d];
                s1 += a * a; s2 += b * b;
            }
            nq[tid] = sqrtf(s1); nk[tid] = sqrtf(s2);
        } else {
            nq[tid] = 1.f; nk[tid] = 1.f;
        }
    }
    __syncthreads();

    float tauh = fmaxf(tau[hh], 0.01f);
    const float* bh = &g_bias[hh * (T_ * T_)];
    if (tid < 169) {
        int q0 = (tid / 13) * 4, k0 = (tid % 13) * 4;
        float acc[4][4];
        #pragma unroll
        for (int i = 0; i < 4; i++)
            #pragma unroll
            for (int j = 0; j < 4; j++) acc[i][j] = 0.f;
        #pragma unroll
        for (int d4 = 0; d4 < 8; d4++) {
            float4 qv[4], kv[4];
            #pragma unroll
            for (int i = 0; i < 4; i++)
                qv[i] = *(const float4*)&sq[(q0 + i) * SQS + d4 * 4];
            #pragma unroll
            for (int j = 0; j < 4; j++)
                kv[j] = *(const float4*)&sk[(k0 + j) * SQS + d4 * 4];
            #pragma unroll
            for (int i = 0; i < 4; i++)
                #pragma unroll
                for (int j = 0; j < 4; j++)
                    acc[i][j] += qv[i].x * kv[j].x + qv[i].y * kv[j].y
                               + qv[i].z * kv[j].z + qv[i].w * kv[j].w;
        }
        #pragma unroll
        for (int i = 0; i < 4; i++) {
            int q = q0 + i;
            if (q >= T_) break;
            #pragma unroll
            for (int j = 0; j < 4; j++) {
                int k = k0 + j;
                if (k >= T_) continue;
                float s = acc[i][j] / fmaxf(nq[q] * nk[k], 1e-6f) / tauh
                        + bh[q * T_ + k];
                if (rg[q] != rg[k]) s -= 100.0f;
                ss[q * 50 + k] = s;
            }
        }
    }
    __syncthreads();

    if (tid < T_) {
        float m = -1e30f;
        for (int k = 0; k < T_; k++) m = fmaxf(m, ss[tid * 50 + k]);
        float sum = 0.f;
        for (int k = 0; k < T_; k++) {
            float e = expf(ss[tid * 50 + k] - m);
            ss[tid * 50 + k] = e; sum += e;
        }
        float inv = 1.f / sum;
        for (int k = 0; k < T_; k++) ss[tid * 50 + k] *= inv;
    }
    __syncthreads();

    if (tid < 200) {
        int t0 = (tid / 8) * 2, d4 = tid % 8;
        float4 a0 = make_float4(0.f, 0.f, 0.f, 0.f), a1 = a0;
        for (int k = 0; k < T_; k++) {
            float s0 = ss[t0 * 50 + k];
            float s1 = ss[(t0 + 1) * 50 + k];
            float4 v = *(const float4*)&sv[k * SQS + d4 * 4];
            a0.x += s0 * v.x; a0.y += s0 * v.y; a0.z += s0 * v.z; a0.w += s0 * v.w;
            a1.x += s1 * v.x; a1.y += s1 * v.y; a1.z += s1 * v.z; a1.w += s1 * v.w;
        }
        __half* op = g_o1 + (size_t)(bw * T_ + t0) * CC + hh * HD_ + d4 * 4;
        ((__half2*)op)[0] = __floats2half2_rn(a0.x, a0.y);
        ((__half2*)op)[1] = __floats2half2_rn(a0.z, a0.w);
        if (t0 + 1 < T_) {
            __half* op1 = op + CC;
            ((__half2*)op1)[0] = __floats2half2_rn(a1.x, a1.y);
            ((__half2*)op1)[1] = __floats2half2_rn(a1.z, a1.w);
        }
    }
}

// ---------------- fold+roll(+3) + LN1 + residual; emit CA query tokens ------
__global__ __launch_bounds__(256)
void merge_ln1(const float* __restrict__ visual,
               const float* __restrict__ g, const float* __restrict__ bt) {
    int pos = blockIdx.x;
    int b = pos / HWSZ, hw = pos % HWSZ;
    int h = hw / WW_, w = hw % WW_;
    int hp = (h + HH - SS_) % HH, wp = (w + WW_ - SS_) % WW_;
    int rm = (b * NW_ + (hp / WS_) * 8 + (wp / WS_)) * T_ + (hp % WS_) * WS_ + (wp % WS_);

    __shared__ float x[CC];
    int tid = threadIdx.x;
    float s = 0.f, ss2 = 0.f;
    for (int c = tid; c < CC; c += 256) {
        float v = __half2float(g_w2[(size_t)rm * CC + c]);
        x[c] = v; s += v; ss2 += v * v;
    }
    float mu, rstd;
    block_meanvar(s, ss2, CC, &mu, &rstd);
    for (int c = tid; c < CC; c += 256) {
        float v = (x[c] - mu) * rstd * g[c] + bt[c]
                + visual[(size_t)(b * CC + c) * HWSZ + hw];
        __half hv = __float2half_rn(v);
        g_skipa[(size_t)pos * CC + c] = hv;
        g_pq  [(size_t)rm  * CC + c] = hv;
    }
}

// ---------------- cross attention (register-blocked, vector loads) ----------
__global__ __launch_bounds__(256)
void ca_attn() {
    int bw = blockIdx.x >> 4;
    int hh = blockIdx.x & 15;
    int bkv = bw & 7;
    int tid = threadIdx.x;

    __shared__ __align__(16) float sq[52 * SQS], sk[L_ * SQS], sv[L_ * SQS];
    __shared__ float ss[50 * 65];

    for (int i = tid; i < 3 * 32; i += 256) {
        int r = 49 + i / 32, c = i % 32;
        sq[r * SQS + c] = 0.f;
    }
    if (tid < T_ * 4) {
        int t = tid >> 2, sg = tid & 3;
        h8_to_f(g_q2 + (size_t)(bw * T_ + t) * CC + hh * HD_ + sg * 8,
                &sq[t * SQS + sg * 8]);
    }
    {
        int l = tid >> 2, sg = tid & 3;      // 256 = 64*4 exactly
        size_t ro = (size_t)(bkv * L_ + l) * (2 * CC) + hh * HD_ + sg * 8;
        h8_to_f(g_kv2 + ro,      &sk[l * SQS + sg * 8]);
        h8_to_f(g_kv2 + ro + CC, &sv[l * SQS + sg * 8]);
    }
    __syncthreads();

    if (tid < 208) {
        int q0 = (tid / 16) * 4, l0 = (tid % 16) * 4;
        float acc[4][4];
        #pragma unroll
        for (int i = 0; i < 4; i++)
            #pragma unroll
            for (int j = 0; j < 4; j++) acc[i][j] = 0.f;
        #pragma unroll
        for (int d4 = 0; d4 < 8; d4++) {
            float4 qv[4], kv[4];
            #pragma unroll
            for (int i = 0; i < 4; i++)
                qv[i] = *(const float4*)&sq[(q0 + i) * SQS + d4 * 4];
            #pragma unroll
            for (int j = 0; j < 4; j++)
                kv[j] = *(const float4*)&sk[(l0 + j) * SQS + d4 * 4];
            #pragma unroll
            for (int i = 0; i < 4; i++)
                #pragma unroll
                for (int j = 0; j < 4; j++)
                    acc[i][j] += qv[i].x * kv[j].x + qv[i].y * kv[j].y
                               + qv[i].z * kv[j].z + qv[i].w * kv[j].w;
        }
        #pragma unroll
        for (int i = 0; i < 4; i++) {
            int q = q0 + i;
            if (q >= T_) break;
            #pragma unroll
            for (int j = 0; j < 4; j++)
                ss[q * 65 + l0 + j] = acc[i][j];
        }
    }
    __syncthreads();

    if (tid < T_) {
        float m = -1e30f;
        for (int l = 0; l < L_; l++) m = fmaxf(m, ss[tid * 65 + l]);
        float sum = 0.f;
        for (int l = 0; l < L_; l++) {
            float e = expf(ss[tid * 65 + l] - m);
            ss[tid * 65 + l] = e; sum += e;
        }
        float inv = 1.f / sum;
        for (int l = 0; l < L_; l++) ss[tid * 65 + l] *= inv;
    }
    __syncthreads();

    if (tid < 200) {
        int t0 = (tid / 8) * 2, d4 = tid % 8;
        float4 a0 = make_float4(0.f, 0.f, 0.f, 0.f), a1 = a0;
        for (int l = 0; l < L_; l++) {
            float s0 = ss[t0 * 65 + l];
            float s1 = ss[(t0 + 1) * 65 + l];
            float4 v = *(const float4*)&sv[l * SQS + d4 * 4];
            a0.x += s0 * v.x; a0.y += s0 * v.y; a0.z += s0 * v.z; a0.w += s0 * v.w;
            a1.x += s1 * v.x; a1.y += s1 * v.y; a1.z += s1 * v.z; a1.w += s1 * v.w;
        }
        __half* op = g_co1 + (size_t)(bw * T_ + t0) * CC + hh * HD_ + d4 * 4;
        ((__half2*)op)[0] = __floats2half2_rn(a0.x, a0.y);
        ((__half2*)op)[1] = __floats2half2_rn(a0.z, a0.w);
        if (t0 + 1 < T_) {
            __half* op1 = op + CC;
            ((__half2*)op1)[0] = __floats2half2_rn(a1.x, a1.y);
            ((__half2*)op1)[1] = __floats2half2_rn(a1.z, a1.w);
        }
    }
}

// ---------------- LN2 + fold+roll(+3) + residual (warp-per-row, coalesced) --
__global__ __launch_bounds__(256)
void ca_ln2(const float* __restrict__ g, const float* __restrict__ bt) {
    int r = blockIdx.x * 8 + (threadIdx.x >> 5);
    int lane = threadIdx.x & 31;
    int bw = r / T_, t = r % T_;
    int b = bw / NW_, win = bw % NW_, wh = win >> 3, ww = win & 7;
    int h = (wh * WS_ + t / WS_ + SS_) % HH;
    int w = (ww * WS_ + t % WS_ + SS_) % WW_;
    int pos = b * HWSZ + h * WW_ + w;

    int c0 = lane * 16;
    float x[16];
    h8_to_f(g_co2 + (size_t)r * CC + c0,     x);
    h8_to_f(g_co2 + (size_t)r * CC + c0 + 8, x + 8);

    float s = 0.f, ss = 0.f;
    #pragma unroll
    for (int i = 0; i < 16; i++) { s += x[i]; ss += x[i] * x[i]; }
    float mu, rstd;
    warp_meanvar(s, ss, CC, &mu, &rstd);

    float sa[16];
    h8_to_f(g_skipa + (size_t)pos * CC + c0,     sa);
    h8_to_f(g_skipa + (size_t)pos * CC + c0 + 8, sa + 8);

    __half* sp = g_skip2 + (size_t)pos * CC + c0;
    #pragma unroll
    for (int i = 0; i < 16; i += 2) {
        float v0 = (x[i]     - mu) * rstd * g[c0 + i]     + bt[c0 + i]     + sa[i];
        float v1 = (x[i + 1] - mu) * rstd * g[c0 + i + 1] + bt[c0 + i + 1] + sa[i + 1];
        *(__half2*)(sp + i) = __floats2half2_rn(v0, v1);
    }
}

// ---------------- LN3(ff) + skip2, write [B,C,H,W] ----------------
__global__ __launch_bounds__(256)
void final_kernel(float* __restrict__ out,
                  const float* __restrict__ g, const float* __restrict__ bt) {
    int pos = blockIdx.x;
    int b = pos / HWSZ, hw = pos % HWSZ;

    __shared__ float x[CC];
    int tid = threadIdx.x;
    float s = 0.f, ss2 = 0.f;
    for (int c = tid; c < CC; c += 256) {
        float v = __half2float(g_ffo[(size_t)pos * CC + c]);
        x[c] = v; s += v; ss2 += v * v;
    }
    float mu, rstd;
    block_meanvar(s, ss2, CC, &mu, &rstd);
    for (int c = tid; c < CC; c += 256) {
        float v = (x[c] - mu) * rstd * g[c] + bt[c];
        out[(size_t)(b * CC + c) * HWSZ + hw] =
            __half2float(g_skip2[(size_t)pos * CC + c]) + v;
    }
}

// ---------------- launch ----------------
extern "C" void kernel_launch(void* const* d_in, const int* in_sizes, int n_in,
                              void* d_out, int out_size) {
    const float* visual   = (const float*)d_in[0];
    const float* vector   = (const float*)d_in[1];
    const float* tm_w     = (const float*)d_in[2];
    const float* tm_b     = (const float*)d_in[3];
    const float* ln1_g    = (const float*)d_in[4];
    const float* ln1_b    = (const float*)d_in[5];
    const float* ln2_g    = (const float*)d_in[6];
    const float* ln2_b    = (const float*)d_in[7];
    const float* ln3_g    = (const float*)d_in[8];
    const float* ln3_b    = (const float*)d_in[9];
    const float* qkv_w    = (const float*)d_in[10];
    const float* qkv_b    = (const float*)d_in[11];
    const float* wproj_w  = (const float*)d_in[12];
    const float* wproj_b  = (const float*)d_in[13];
    const float* meta_w1  = (const float*)d_in[14];
    const float* meta_b1  = (const float*)d_in[15];
    const float* meta_w2  = (const float*)d_in[16];
    const float* meta_b2  = (const float*)d_in[17];
    const float* tau      = (const float*)d_in[18];
    const float* ca_in_w  = (const float*)d_in[19];
    const float* ca_in_b  = (const float*)d_in[20];
    const float* ca_out_w = (const float*)d_in[21];
    const float* ca_out_b = (const float*)d_in[22];
    const float* ff_w1    = (const float*)d_in[23];
    const float* ff_b1    = (const float*)d_in[24];
    const float* ff_w2    = (const float*)d_in[25];
    const float* ff_b2    = (const float*)d_in[26];
    float* out = (float*)d_out;

    __half *vin, *vec, *tok, *o1, *pq, *co1, *sk2, *ffh;
    __half *qkv, *w2, *q2, *kv2, *co2, *ffo;
    __half *tmwt, *qkvwt, *wprwt, *caint, *caoutt, *ff1t, *ff2t;
    cudaGetSymbolAddress((void**)&vin,   g_vin);
    cudaGetSymbolAddress((void**)&vec,   g_vec);
    cudaGetSymbolAddress((void**)&tok,   g_tok);
    cudaGetSymbolAddress((void**)&qkv,   g_qkv);
    cudaGetSymbolAddress((void**)&o1,    g_o1);
    cudaGetSymbolAddress((void**)&w2,    g_w2);
    cudaGetSymbolAddress((void**)&pq,    g_pq);
    cudaGetSymbolAddress((void**)&q2,    g_q2);
    cudaGetSymbolAddress((void**)&kv2,   g_kv2);
    cudaGetSymbolAddress((void**)&co1,   g_co1);
    cudaGetSymbolAddress((void**)&co2,   g_co2);
    cudaGetSymbolAddress((void**)&sk2,   g_skip2);
    cudaGetSymbolAddress((void**)&ffh,   g_ffh);
    cudaGetSymbolAddress((void**)&ffo,   g_ffo);
    cudaGetSymbolAddress((void**)&tmwt,  g_tmw_t);
    cudaGetSymbolAddress((void**)&qkvwt, g_qkvw_t);
    cudaGetSymbolAddress((void**)&wprwt, g_wprw_t);
    cudaGetSymbolAddress((void**)&caint, g_cain_t);
    cudaGetSymbolAddress((void**)&caoutt,g_caout_t);
    cudaGetSymbolAddress((void**)&ff1t,  g_ff1_t);
    cudaGetSymbolAddress((void**)&ff2t,  g_ff2_t);

    cudaFuncSetAttribute((const void*)tgemm<EPI_NONE,  __half>, cudaFuncAttributeMaxDynamicSharedMemorySize, TGEMM_SMEM);
    cudaFuncSetAttribute((const void*)tgemm<EPI_GELU,  __half>, cudaFuncAttributeMaxDynamicSharedMemorySize, TGEMM_SMEM);
    cudaFuncSetAttribute((const void*)tgemm<EPI_SCALE, __half>, cudaFuncAttributeMaxDynamicSharedMemorySize, TGEMM_SMEM);

    // batched weight transposes (+fp16 rounding)
    TWArgs twa;
    twa.seg[0] = { tm_w,     tmwt,   256,  512,    0 };
    twa.seg[1] = { qkv_w,    qkvwt,  512, 1536,  128 };
    twa.seg[2] = { wproj_w,  wprwt,  512,  512,  896 };
    twa.seg[3] = { ca_in_w,  caint,  512, 1536, 1152 };
    twa.seg[4] = { ca_out_w, caoutt, 512,  512, 1920 };
    twa.seg[5] = { ff_w1,    ff1t,   512, 2048, 2176 };
    twa.seg[6] = { ff_w2,    ff2t,  2048,  512, 3200 };
    twa.total = 4224;
    transpose_all<<<4224, 256>>>(twa);
    half_copy<<<512, 256>>>(vector, vin, 512 * 256);

    bias_kernel<<<T_ * T_, 256>>>(meta_w1, meta_b1, meta_w2, meta_b2);

    // vec = gelu(vector @ tm_w + tm_b)
    tgemm<EPI_GELU, __half><<<dim3(4, 4), 256, TGEMM_SMEM>>>(vin, tmwt, tm_b, vec, 512, 512, 256, 0.f);
    // K2|V2 fused
    tgemm<EPI_NONE, __half><<<dim3(8, 4), 256, TGEMM_SMEM>>>(vec, caint + 512 * 512, ca_in_b + 512, kv2, 512, 1024, 512, 0.f);

    unfold_kernel<<<NTOK, 256>>>(visual);
    tgemm<EPI_NONE, __half><<<dim3(12, 196), 256, TGEMM_SMEM>>>(tok, qkvwt, qkv_b, qkv, NTOK, 3 * CC, CC, 0.f);
    win_attn<<<BW_ * NH_, 256>>>(tau);
    tgemm<EPI_NONE, __half><<<dim3(4, 196), 256, TGEMM_SMEM>>>(o1, wprwt, wproj_b, w2, NTOK, CC, CC, 0.f);
    merge_ln1<<<BB * HWSZ, 256>>>(visual, ln1_g, ln1_b);
    tgemm<EPI_SCALE, __half><<<dim3(4, 196), 256, TGEMM_SMEM>>>(pq, caint, ca_in_b, q2, NTOK, CC, CC, 0.17677669529663687f);
    ca_attn<<<BW_ * NH_, 256>>>();
    tgemm<EPI_NONE, __half><<<dim3(4, 196), 256, TGEMM_SMEM>>>(co1, caoutt, ca_out_b, co2, NTOK, CC, CC, 0.f);
    ca_ln2<<<NTOK / 8, 256>>>(ln2_g, ln2_b);
    tgemm<EPI_GELU, __half><<<dim3(16, 196), 256, TGEMM_SMEM>>>(sk2, ff1t, ff_b1, ffh, NTOK, 4 * CC, CC, 0.f);
    tgemm<EPI_NONE, __half><<<dim3(4, 196), 256, TGEMM_SMEM>>>(ffh, ff2t, ff_b2, ffo, NTOK, CC, 2048, 0.f);
    final_kernel<<<BB * HWSZ, 256>>>(out, ln3_g, ln3_b);
}

// round 16
// speedup vs baseline: 1.1314x; 1.0537x over previous
#include <cuda_runtime.h>
#include <cuda_fp16.h>
#include <math.h>
#include <stdint.h>

// Problem constants
#define BB    8
#define CC    512
#define HH    56
#define WW_   56
#define HWSZ  3136
#define WS_   7
#define SS_   3
#define NH_   16
#define HD_   32
#define T_    49
#define NW_   64
#define BW_   512          // BB * NW_
#define NTOK  25088        // BW_ * T_
#define L_    64

// ---------------- scratch (device globals; no runtime alloc) ----------------
__device__ __align__(16) __half g_vin [512 * 256];
__device__ __align__(16) __half g_vec [BW_ * CC];
__device__ __align__(16) __half g_tok [NTOK * CC];
__device__ __align__(16) __half g_qkv [NTOK * 3 * CC];
__device__ __align__(16) __half g_o1  [NTOK * CC];
__device__ __align__(16) __half g_w2  [NTOK * CC];
__device__ __align__(16) __half g_skipa[NTOK * CC];     // skip1 fp16
__device__ __align__(16) __half g_pq  [NTOK * CC];
__device__ __align__(16) __half g_q2  [NTOK * CC];
__device__ __align__(16) __half g_kv2 [BW_ * 2 * CC];   // [B*L, 1024]: k | v
__device__ __align__(16) __half g_co1 [NTOK * CC];
__device__ __align__(16) __half g_co2 [NTOK * CC];
__device__ __align__(16) __half g_skip2[NTOK * CC];     // fp16 (GEMM A + residual)
__device__ __align__(16) __half g_ffh [NTOK * 4 * CC];
__device__ __align__(16) __half g_ffo [NTOK * CC];
__device__ float  g_bias[NH_ * T_ * T_];

// transposed (fp16) weights: [N, K] K-contiguous
__device__ __align__(16) __half g_tmw_t  [512 * 256];
__device__ __align__(16) __half g_qkvw_t [1536 * 512];
__device__ __align__(16) __half g_wprw_t [512 * 512];
__device__ __align__(16) __half g_cain_t [1536 * 512];
__device__ __align__(16) __half g_caout_t[512 * 512];
__device__ __align__(16) __half g_ff1_t  [2048 * 512];
__device__ __align__(16) __half g_ff2_t  [512 * 2048];

// ---------------- helpers ----------------
__device__ __forceinline__ float gelu_exact(float x) {
    return 0.5f * x * (1.0f + erff(x * 0.70710678118654752f));
}
__device__ __forceinline__ uint32_t s2u(const void* p) {
    uint32_t a;
    asm("{ .reg .u64 t; cvta.to.shared.u64 t, %1; cvt.u32.u64 %0, t; }"
        : "=r"(a) : "l"(p));
    return a;
}

__device__ __forceinline__ void block_meanvar(float s, float ss, int n,
                                              float* mu, float* rstd) {
    #pragma unroll
    for (int o = 16; o > 0; o >>= 1) {
        s  += __shfl_down_sync(0xffffffffu, s,  o);
        ss += __shfl_down_sync(0xffffffffu, ss, o);
    }
    __shared__ float rs[8], rss[8], res[2];
    int lane = threadIdx.x & 31, wid = threadIdx.x >> 5;
    if (lane == 0) { rs[wid] = s; rss[wid] = ss; }
    __syncthreads();
    if (threadIdx.x == 0) {
        float S = 0.f, SS2 = 0.f;
        #pragma unroll
        for (int i = 0; i < 8; i++) { S += rs[i]; SS2 += rss[i]; }
        float m = S / n;
        float var = SS2 / n - m * m;
        res[0] = m; res[1] = rsqrtf(var + 1e-5f);
    }
    __syncthreads();
    *mu = res[0]; *rstd = res[1];
}

__device__ __forceinline__ void warp_meanvar(float s, float ss, int n,
                                             float* mu, float* rstd) {
    #pragma unroll
    for (int o = 16; o > 0; o >>= 1) {
        s  += __shfl_xor_sync(0xffffffffu, s,  o);
        ss += __shfl_xor_sync(0xffffffffu, ss, o);
    }
    float m = s / n;
    *mu = m;
    *rstd = rsqrtf(ss / n - m * m + 1e-5f);
}

// load 8 fp16 (16B) -> 8 floats
__device__ __forceinline__ void h8_to_f(const __half* src, float* dst) {
    uint4 u = *(const uint4*)src;
    const __half2* h = (const __half2*)&u;
    #pragma unroll
    for (int i = 0; i < 4; i++) {
        float2 f = __half22float2(h[i]);
        dst[2 * i] = f.x; dst[2 * i + 1] = f.y;
    }
}

// ---------------- fp16 mma.sync GEMM (K-chunk 64, 2-stage + ldmatrix) -------
#define EPI_NONE  0
#define EPI_GELU  1
#define EPI_SCALE 2

#define LDPAD_H 72
#define TILEH (128 * LDPAD_H)            // halves per tile (64-K chunk)
#define TGEMM_SMEM (4 * TILEH * 2)       // 2 stages x (A+B), bytes = 73728

__device__ __forceinline__ void mma_f16(float* c, const uint32_t* a,
                                        const uint32_t* b) {
    asm volatile(
        "mma.sync.aligned.m16n8k16.row.col.f32.f16.f16.f32 "
        "{%0,%1,%2,%3}, {%4,%5,%6,%7}, {%8,%9}, {%0,%1,%2,%3};"
        : "+f"(c[0]), "+f"(c[1]), "+f"(c[2]), "+f"(c[3])
        : "r"(a[0]), "r"(a[1]), "r"(a[2]), "r"(a[3]),
          "r"(b[0]), "r"(b[1]));
}

#define LDSM_X4(r0, r1, r2, r3, addr) \
    asm volatile("ldmatrix.sync.aligned.m8n8.x4.shared.b16 {%0,%1,%2,%3}, [%4];" \
        : "=r"(r0), "=r"(r1), "=r"(r2), "=r"(r3) : "r"(addr))

__device__ __forceinline__ void store2(float* p, float a, float b) {
    *(float2*)p = make_float2(a, b);
}
__device__ __forceinline__ void store2(__half* p, float a, float b) {
    *(__half2*)p = __floats2half2_rn(a, b);
}

template <int EPI, typename OutT>
__global__ __launch_bounds__(256, 2)
void tgemm(const __half* __restrict__ A, const __half* __restrict__ W,
           const float* __restrict__ bias, OutT* __restrict__ C,
           int M, int N, int K, float alpha) {
    extern __shared__ __half smh[];
    __half* Abuf = smh;                  // [2][128][LDPAD_H]
    __half* Bbuf = smh + 2 * TILEH;      // [2][128][LDPAD_H]
    const uint32_t sm_a = s2u(Abuf), sm_b = s2u(Bbuf);

    const int tid = threadIdx.x;
    const int wid = tid >> 5, lane = tid & 31;
    const int m0 = blockIdx.y << 7, n0 = blockIdx.x << 7;
    const int wm = wid & 3, wn = wid >> 2;
    const int m_off = wm << 5;           // 32-row warp tile
    const int n_off = wn << 6;           // 64-col warp tile

    const __half* Abase = A + (size_t)m0 * K;
    const __half* Wbase = W + (size_t)n0 * K;
    const int NC = K >> 6;               // 64-K chunks

    const int seg = tid & 7;             // 8 x 16B (8-half) segments per row
    const int lr0 = tid >> 3;            // 0..31

    auto load_chunk = [&](int c, int sel) {
        uint32_t ab = sm_a + sel * (TILEH * 2);
        uint32_t bb = sm_b + sel * (TILEH * 2);
        const __half* As = Abase + c * 64 + seg * 8;
        const __half* Ws = Wbase + c * 64 + seg * 8;
        #pragma unroll
        for (int i = 0; i < 4; i++) {
            int r = lr0 + (i << 5);      // 0..127
            uint32_t so = (uint32_t)(r * (LDPAD_H * 2) + seg * 16);
            asm volatile("cp.async.cg.shared.global [%0], [%1], 16;"
                         :: "r"(ab + so), "l"(As + (size_t)r * K));
            asm volatile("cp.async.cg.shared.global [%0], [%1], 16;"
                         :: "r"(bb + so), "l"(Ws + (size_t)r * K));
        }
        asm volatile("cp.async.commit_group;" ::: "memory");
    };

    const int lm = lane >> 3, lr = lane & 7;
    uint32_t a_off[2], b_off[4];
    #pragma unroll
    for (int mt = 0; mt < 2; mt++) {
        int row = m_off + mt * 16 + lr + (lm & 1) * 8;
        int koff = (lm >> 1) * 8;
        a_off[mt] = (uint32_t)((row * LDPAD_H + koff) * 2);
    }
    #pragma unroll
    for (int g = 0; g < 4; g++) {
        int row = n_off + (2 * g + (lm >> 1)) * 8 + lr;
        int koff = (lm & 1) * 8;
        b_off[g] = (uint32_t)((row * LDPAD_H + koff) * 2);
    }

    float acc[2][8][4];
    #pragma unroll
    for (int i = 0; i < 2; i++)
        #pragma unroll
        for (int j = 0; j < 8; j++)
            #pragma unroll
            for (int q = 0; q < 4; q++) acc[i][j][q] = 0.f;

    load_chunk(0, 0);

    const int qr = lane >> 2, qc = lane & 3;

    for (int c = 0; c < NC; c++) {
        int sel = c & 1;
        asm volatile("cp.async.wait_group 0;" ::: "memory");
        __syncthreads();                 // chunk c arrived; prior buffer free
        if (c + 1 < NC) load_chunk(c + 1, sel ^ 1);

        const uint32_t abase = sm_a + sel * (TILEH * 2);
        const uint32_t bbase = sm_b + sel * (TILEH * 2);

        #pragma unroll
        for (int ks = 0; ks < 4; ks++) {
            const uint32_t kb = ks * 32;      // 16 halves = 32 bytes
            uint32_t a[2][4], b[8][2];
            #pragma unroll
            for (int mt = 0; mt < 2; mt++)
                LDSM_X4(a[mt][0], a[mt][1], a[mt][2], a[mt][3],
                        abase + a_off[mt] + kb);
            #pragma unroll
            for (int g = 0; g < 4; g++)
                LDSM_X4(b[2 * g][0], b[2 * g][1], b[2 * g + 1][0], b[2 * g + 1][1],
                        bbase + b_off[g] + kb);
            #pragma unroll
            for (int mt = 0; mt < 2; mt++)
                #pragma unroll
                for (int nt = 0; nt < 8; nt++)
                    mma_f16(acc[mt][nt], a[mt], b[nt]);
        }
        __syncthreads();                 // all warps done before buffer reuse
    }

    #pragma unroll
    for (int mt = 0; mt < 2; mt++) {
        #pragma unroll
        for (int half = 0; half < 2; half++) {
            int row = m0 + m_off + mt * 16 + qr + half * 8;
            OutT* Cp = C + (size_t)row * N + n0 + n_off;
            #pragma unroll
            for (int nt = 0; nt < 8; nt++) {
                int col = nt * 8 + qc * 2;
                float v0 = acc[mt][nt][half * 2 + 0] + bias[n0 + n_off + col];
                float v1 = acc[mt][nt][half * 2 + 1] + bias[n0 + n_off + col + 1];
                if (EPI == EPI_GELU)  { v0 = gelu_exact(v0); v1 = gelu_exact(v1); }
                if (EPI == EPI_SCALE) { v0 *= alpha; v1 *= alpha; }
                store2(Cp + col, v0, v1);
            }
        }
    }
}

// ---------------- batched weight transpose + fp16 ----------------
struct TWSeg { const float* src; __half* dst; int K; int N; int tile0; };
struct TWArgs { TWSeg seg[7]; int total; };

__global__ __launch_bounds__(256)
void transpose_all(TWArgs a) {
    int bid = blockIdx.x;
    int si = 0;
    #pragma unroll
    for (int i = 1; i < 7; i++)
        if (bid >= a.seg[i].tile0) si = i;
    const TWSeg sg = a.seg[si];
    int local = bid - sg.tile0;
    int tilesX = sg.N >> 5;
    int nb = (local % tilesX) << 5;
    int kb = (local / tilesX) << 5;

    __shared__ float tile[32][33];
    int tx = threadIdx.x & 31, ty = threadIdx.x >> 5;
    #pragma unroll
    for (int i = 0; i < 32; i += 8)
        tile[ty + i][tx] = sg.src[(size_t)(kb + ty + i) * sg.N + nb + tx];
    __syncthreads();
    #pragma unroll
    for (int i = 0; i < 32; i += 8)
        sg.dst[(size_t)(nb + ty + i) * sg.K + kb + tx] =
            __float2half_rn(tile[tx][ty + i]);
}

__global__ void half_copy(const float* __restrict__ in, __half* __restrict__ o, int n) {
    int i = blockIdx.x * 256 + threadIdx.x;
    if (i < n) o[i] = __float2half_rn(in[i]);
}

// ---------------- relative-position bias precompute ----------------
__global__ void bias_kernel(const float* __restrict__ w1, const float* __restrict__ b1,
                            const float* __restrict__ w2, const float* __restrict__ b2) {
    int pair = blockIdx.x;
    int q = pair / T_, k = pair % T_;
    float d0 = (float)(q / WS_ - k / WS_);
    float d1 = (float)(q % WS_ - k % WS_);
    float r0 = (d0 > 0.f ? 1.f : (d0 < 0.f ? -1.f : 0.f)) * log1pf(fabsf(d0));
    float r1 = (d1 > 0.f ? 1.f : (d1 < 0.f ? -1.f : 0.f)) * log1pf(fabsf(d1));
    int tid = threadIdx.x;
    __shared__ float hbuf[256];
    float hv = r0 * w1[tid] + r1 * w1[256 + tid] + b1[tid];
    hbuf[tid] = fmaxf(hv, 0.f);
    __syncthreads();
    if (tid < NH_) {
        float s = b2[tid];
        #pragma unroll 8
        for (int j = 0; j < 256; j++) s += hbuf[j] * w2[j * NH_ + tid];
        g_bias[tid * (T_ * T_) + pair] = s;
    }
}

// ---------------- roll(-3,-3) + unfold into token rows (fp16) ---------------
__global__ __launch_bounds__(256)
void unfold_kernel(const float* __restrict__ visual) {
    int r = blockIdx.x;
    int bw = r / T_, t = r % T_;
    int b = bw / NW_, win = bw % NW_, wh = win >> 3, ww = win & 7;
    int h = (wh * WS_ + t / WS_ + SS_) % HH;
    int w = (ww * WS_ + t % WS_ + SS_) % WW_;
    int hw = h * WW_ + w;
    for (int c = threadIdx.x; c < CC; c += 256)
        g_tok[(size_t)r * CC + c] = __float2half_rn(visual[(size_t)(b * CC + c) * HWSZ + hw]);
}

// ---------------- window attention (register-blocked, vector loads) ---------
#define SQS 36   // padded row stride (floats)
__global__ __launch_bounds__(256)
void win_attn(const float* __restrict__ tau) {
    int bw = blockIdx.x >> 4;
    int hh = blockIdx.x & 15;
    int tid = threadIdx.x;

    __shared__ __align__(16) float sq[52 * SQS], sk[52 * SQS], sv[52 * SQS];
    __shared__ float ss[50 * 50];
    __shared__ float nq[52], nk[52];
    __shared__ int   rg[T_];

    for (int i = tid; i < 3 * 32; i += 256) {
        int r = 49 + i / 32, c = i % 32;
        sq[r * SQS + c] = 0.f; sk[r * SQS + c] = 0.f; sv[r * SQS + c] = 0.f;
    }

    if (tid < T_ * 4) {
        int t = tid >> 2, sg = tid & 3;
        size_t ro = (size_t)(bw * T_ + t) * (3 * CC) + hh * HD_ + sg * 8;
        h8_to_f(g_qkv + ro,           &sq[t * SQS + sg * 8]);
        h8_to_f(g_qkv + ro + CC,      &sk[t * SQS + sg * 8]);
        h8_to_f(g_qkv + ro + 2 * CC,  &sv[t * SQS + sg * 8]);
    }
    int win = bw & 63, wh = win >> 3, ww = win & 7;
    if (tid < T_) {
        int row = wh * WS_ + tid / WS_;
        int col = ww * WS_ + tid % WS_;
        int rh = row < 49 ? 0 : (row < 53 ? 1 : 2);
        int rw = col < 49 ? 0 : (col < 53 ? 1 : 2);
        rg[tid] = rh * 3 + rw;
    }
    __syncthreads();

    if (tid < 52) {
        if (tid < T_) {
            float s1 = 0.f, s2 = 0.f;
            #pragma unroll
            for (int d = 0; d < HD_; d++) {
                float a = sq[tid * SQS + d], b = sk[tid * SQS + d];
                s1 += a * a; s2 += b * b;
            }
            nq[tid] = sqrtf(s1); nk[tid] = sqrtf(s2);
        } else {
            nq[tid] = 1.f; nk[tid] = 1.f;
        }
    }
    __syncthreads();

    float tauh = fmaxf(tau[hh], 0.01f);
    const float* bh = &g_bias[hh * (T_ * T_)];
    if (tid < 169) {
        int q0 = (tid / 13) * 4, k0 = (tid % 13) * 4;
        float acc[4][4];
        #pragma unroll
        for (int i = 0; i < 4; i++)
            #pragma unroll
            for (int j = 0; j < 4; j++) acc[i][j] = 0.f;
        #pragma unroll
        for (int d4 = 0; d4 < 8; d4++) {
            float4 qv[4], kv[4];
            #pragma unroll
            for (int i = 0; i < 4; i++)
                qv[i] = *(const float4*)&sq[(q0 + i) * SQS + d4 * 4];
            #pragma unroll
            for (int j = 0; j < 4; j++)
                kv[j] = *(const float4*)&sk[(k0 + j) * SQS + d4 * 4];
            #pragma unroll
            for (int i = 0; i < 4; i++)
                #pragma unroll
                for (int j = 0; j < 4; j++)
                    acc[i][j] += qv[i].x * kv[j].x + qv[i].y * kv[j].y
                               + qv[i].z * kv[j].z + qv[i].w * kv[j].w;
        }
        #pragma unroll
        for (int i = 0; i < 4; i++) {
            int q = q0 + i;
            if (q >= T_) break;
            #pragma unroll
            for (int j = 0; j < 4; j++) {
                int k = k0 + j;
                if (k >= T_) continue;
                float s = acc[i][j] / fmaxf(nq[q] * nk[k], 1e-6f) / tauh
                        + bh[q * T_ + k];
                if (rg[q] != rg[k]) s -= 100.0f;
                ss[q * 50 + k] = s;
            }
        }
    }
    __syncthreads();

    if (tid < T_) {
        float m = -1e30f;
        for (int k = 0; k < T_; k++) m = fmaxf(m, ss[tid * 50 + k]);
        float sum = 0.f;
        for (int k = 0; k < T_; k++) {
            float e = expf(ss[tid * 50 + k] - m);
            ss[tid * 50 + k] = e; sum += e;
        }
        float inv = 1.f / sum;
        for (int k = 0; k < T_; k++) ss[tid * 50 + k] *= inv;
    }
    __syncthreads();

    if (tid < 200) {
        int t0 = (tid / 8) * 2, d4 = tid % 8;
        float4 a0 = make_float4(0.f, 0.f, 0.f, 0.f), a1 = a0;
        for (int k = 0; k < T_; k++) {
            float s0 = ss[t0 * 50 + k];
            float s1 = ss[(t0 + 1) * 50 + k];
            float4 v = *(const float4*)&sv[k * SQS + d4 * 4];
            a0.x += s0 * v.x; a0.y += s0 * v.y; a0.z += s0 * v.z; a0.w += s0 * v.w;
            a1.x += s1 * v.x; a1.y += s1 * v.y; a1.z += s1 * v.z; a1.w += s1 * v.w;
        }
        __half* op = g_o1 + (size_t)(bw * T_ + t0) * CC + hh * HD_ + d4 * 4;
        ((__half2*)op)[0] = __floats2half2_rn(a0.x, a0.y);
        ((__half2*)op)[1] = __floats2half2_rn(a0.z, a0.w);
        if (t0 + 1 < T_) {
            __half* op1 = op + CC;
            ((__half2*)op1)[0] = __floats2half2_rn(a1.x, a1.y);
            ((__half2*)op1)[1] = __floats2half2_rn(a1.z, a1.w);
        }
    }
}

// ---------------- fold+roll(+3) + LN1 + residual; emit CA query tokens ------
__global__ __launch_bounds__(256)
void merge_ln1(const float* __restrict__ visual,
               const float* __restrict__ g, const float* __restrict__ bt) {
    int pos = blockIdx.x;
    int b = pos / HWSZ, hw = pos % HWSZ;
    int h = hw / WW_, w = hw % WW_;
    int hp = (h + HH - SS_) % HH, wp = (w + WW_ - SS_) % WW_;
    int rm = (b * NW_ + (hp / WS_) * 8 + (wp / WS_)) * T_ + (hp % WS_) * WS_ + (wp % WS_);

    __shared__ float x[CC];
    int tid = threadIdx.x;
    float s = 0.f, ss2 = 0.f;
    for (int c = tid; c < CC; c += 256) {
        float v = __half2float(g_w2[(size_t)rm * CC + c]);
        x[c] = v; s += v; ss2 += v * v;
    }
    float mu, rstd;
    block_meanvar(s, ss2, CC, &mu, &rstd);
    for (int c = tid; c < CC; c += 256) {
        float v = (x[c] - mu) * rstd * g[c] + bt[c]
                + visual[(size_t)(b * CC + c) * HWSZ + hw];
        __half hv = __float2half_rn(v);
        g_skipa[(size_t)pos * CC + c] = hv;
        g_pq  [(size_t)rm  * CC + c] = hv;
    }
}

// ---------------- cross attention (register-blocked, vector loads) ----------
__global__ __launch_bounds__(256)
void ca_attn() {
    int bw = blockIdx.x >> 4;
    int hh = blockIdx.x & 15;
    int bkv = bw & 7;
    int tid = threadIdx.x;

    __shared__ __align__(16) float sq[52 * SQS], sk[L_ * SQS], sv[L_ * SQS];
    __shared__ float ss[50 * 65];

    for (int i = tid; i < 3 * 32; i += 256) {
        int r = 49 + i / 32, c = i % 32;
        sq[r * SQS + c] = 0.f;
    }
    if (tid < T_ * 4) {
        int t = tid >> 2, sg = tid & 3;
        h8_to_f(g_q2 + (size_t)(bw * T_ + t) * CC + hh * HD_ + sg * 8,
                &sq[t * SQS + sg * 8]);
    }
    {
        int l = tid >> 2, sg = tid & 3;      // 256 = 64*4 exactly
        size_t ro = (size_t)(bkv * L_ + l) * (2 * CC) + hh * HD_ + sg * 8;
        h8_to_f(g_kv2 + ro,      &sk[l * SQS + sg * 8]);
        h8_to_f(g_kv2 + ro + CC, &sv[l * SQS + sg * 8]);
    }
    __syncthreads();

    if (tid < 208) {
        int q0 = (tid / 16) * 4, l0 = (tid % 16) * 4;
        float acc[4][4];
        #pragma unroll
        for (int i = 0; i < 4; i++)
            #pragma unroll
            for (int j = 0; j < 4; j++) acc[i][j] = 0.f;
        #pragma unroll
        for (int d4 = 0; d4 < 8; d4++) {
            float4 qv[4], kv[4];
            #pragma unroll
            for (int i = 0; i < 4; i++)
                qv[i] = *(const float4*)&sq[(q0 + i) * SQS + d4 * 4];
            #pragma unroll
            for (int j = 0; j < 4; j++)
                kv[j] = *(const float4*)&sk[(l0 + j) * SQS + d4 * 4];
            #pragma unroll
            for (int i = 0; i < 4; i++)
                #pragma unroll
                for (int j = 0; j < 4; j++)
                    acc[i][j] += qv[i].x * kv[j].x + qv[i].y * kv[j].y
                               + qv[i].z * kv[j].z + qv[i].w * kv[j].w;
        }
        #pragma unroll
        for (int i = 0; i < 4; i++) {
            int q = q0 + i;
            if (q >= T_) break;
            #pragma unroll
            for (int j = 0; j < 4; j++)
                ss[q * 65 + l0 + j] = acc[i][j];
        }
    }
    __syncthreads();

    if (tid < T_) {
        float m = -1e30f;
        for (int l = 0; l < L_; l++) m = fmaxf(m, ss[tid * 65 + l]);
        float sum = 0.f;
        for (int l = 0; l < L_; l++) {
            float e = expf(ss[tid * 65 + l] - m);
            ss[tid * 65 + l] = e; sum += e;
        }
        float inv = 1.f / sum;
        for (int l = 0; l < L_; l++) ss[tid * 65 + l] *= inv;
    }
    __syncthreads();

    if (tid < 200) {
        int t0 = (tid / 8) * 2, d4 = tid % 8;
        float4 a0 = make_float4(0.f, 0.f, 0.f, 0.f), a1 = a0;
        for (int l = 0; l < L_; l++) {
            float s0 = ss[t0 * 65 + l];
            float s1 = ss[(t0 + 1) * 65 + l];
            float4 v = *(const float4*)&sv[l * SQS + d4 * 4];
            a0.x += s0 * v.x; a0.y += s0 * v.y; a0.z += s0 * v.z; a0.w += s0 * v.w;
            a1.x += s1 * v.x; a1.y += s1 * v.y; a1.z += s1 * v.z; a1.w += s1 * v.w;
        }
        __half* op = g_co1 + (size_t)(bw * T_ + t0) * CC + hh * HD_ + d4 * 4;
        ((__half2*)op)[0] = __floats2half2_rn(a0.x, a0.y);
        ((__half2*)op)[1] = __floats2half2_rn(a0.z, a0.w);
        if (t0 + 1 < T_) {
            __half* op1 = op + CC;
            ((__half2*)op1)[0] = __floats2half2_rn(a1.x, a1.y);
            ((__half2*)op1)[1] = __floats2half2_rn(a1.z, a1.w);
        }
    }
}

// ---------------- LN2 + fold+roll(+3) + residual (warp-per-row, coalesced) --
__global__ __launch_bounds__(256)
void ca_ln2(const float* __restrict__ g, const float* __restrict__ bt) {
    int r = blockIdx.x * 8 + (threadIdx.x >> 5);
    int lane = threadIdx.x & 31;
    int bw = r / T_, t = r % T_;
    int b = bw / NW_, win = bw % NW_, wh = win >> 3, ww = win & 7;
    int h = (wh * WS_ + t / WS_ + SS_) % HH;
    int w = (ww * WS_ + t % WS_ + SS_) % WW_;
    int pos = b * HWSZ + h * WW_ + w;

    int c0 = lane * 16;
    float x[16];
    h8_to_f(g_co2 + (size_t)r * CC + c0,     x);
    h8_to_f(g_co2 + (size_t)r * CC + c0 + 8, x + 8);

    float s = 0.f, ss = 0.f;
    #pragma unroll
    for (int i = 0; i < 16; i++) { s += x[i]; ss += x[i] * x[i]; }
    float mu, rstd;
    warp_meanvar(s, ss, CC, &mu, &rstd);

    float sa[16];
    h8_to_f(g_skipa + (size_t)pos * CC + c0,     sa);
    h8_to_f(g_skipa + (size_t)pos * CC + c0 + 8, sa + 8);

    __half* sp = g_skip2 + (size_t)pos * CC + c0;
    #pragma unroll
    for (int i = 0; i < 16; i += 2) {
        float v0 = (x[i]     - mu) * rstd * g[c0 + i]     + bt[c0 + i]     + sa[i];
        float v1 = (x[i + 1] - mu) * rstd * g[c0 + i + 1] + bt[c0 + i + 1] + sa[i + 1];
        *(__half2*)(sp + i) = __floats2half2_rn(v0, v1);
    }
}

// ---------------- LN3(ff) + skip2, write [B,C,H,W] ----------------
__global__ __launch_bounds__(256)
void final_kernel(float* __restrict__ out,
                  const float* __restrict__ g, const float* __restrict__ bt) {
    int pos = blockIdx.x;
    int b = pos / HWSZ, hw = pos % HWSZ;

    __shared__ float x[CC];
    int tid = threadIdx.x;
    float s = 0.f, ss2 = 0.f;
    for (int c = tid; c < CC; c += 256) {
        float v = __half2float(g_ffo[(size_t)pos * CC + c]);
        x[c] = v; s += v; ss2 += v * v;
    }
    float mu, rstd;
    block_meanvar(s, ss2, CC, &mu, &rstd);
    for (int c = tid; c < CC; c += 256) {
        float v = (x[c] - mu) * rstd * g[c] + bt[c];
        out[(size_t)(b * CC + c) * HWSZ + hw] =
            __half2float(g_skip2[(size_t)pos * CC + c]) + v;
    }
}

// ---------------- launch ----------------
extern "C" void kernel_launch(void* const* d_in, const int* in_sizes, int n_in,
                              void* d_out, int out_size) {
    const float* visual   = (const float*)d_in[0];
    const float* vector   = (const float*)d_in[1];
    const float* tm_w     = (const float*)d_in[2];
    const float* tm_b     = (const float*)d_in[3];
    const float* ln1_g    = (const float*)d_in[4];
    const float* ln1_b    = (const float*)d_in[5];
    const float* ln2_g    = (const float*)d_in[6];
    const float* ln2_b    = (const float*)d_in[7];
    const float* ln3_g    = (const float*)d_in[8];
    const float* ln3_b    = (const float*)d_in[9];
    const float* qkv_w    = (const float*)d_in[10];
    const float* qkv_b    = (const float*)d_in[11];
    const float* wproj_w  = (const float*)d_in[12];
    const float* wproj_b  = (const float*)d_in[13];
    const float* meta_w1  = (const float*)d_in[14];
    const float* meta_b1  = (const float*)d_in[15];
    const float* meta_w2  = (const float*)d_in[16];
    const float* meta_b2  = (const float*)d_in[17];
    const float* tau      = (const float*)d_in[18];
    const float* ca_in_w  = (const float*)d_in[19];
    const float* ca_in_b  = (const float*)d_in[20];
    const float* ca_out_w = (const float*)d_in[21];
    const float* ca_out_b = (const float*)d_in[22];
    const float* ff_w1    = (const float*)d_in[23];
    const float* ff_b1    = (const float*)d_in[24];
    const float* ff_w2    = (const float*)d_in[25];
    const float* ff_b2    = (const float*)d_in[26];
    float* out = (float*)d_out;

    __half *vin, *vec, *tok, *o1, *pq, *co1, *sk2, *ffh;
    __half *qkv, *w2, *q2, *kv2, *co2, *ffo;
    __half *tmwt, *qkvwt, *wprwt, *caint, *caoutt, *ff1t, *ff2t;
    cudaGetSymbolAddress((void**)&vin,   g_vin);
    cudaGetSymbolAddress((void**)&vec,   g_vec);
    cudaGetSymbolAddress((void**)&tok,   g_tok);
    cudaGetSymbolAddress((void**)&qkv,   g_qkv);
    cudaGetSymbolAddress((void**)&o1,    g_o1);
    cudaGetSymbolAddress((void**)&w2,    g_w2);
    cudaGetSymbolAddress((void**)&pq,    g_pq);
    cudaGetSymbolAddress((void**)&q2,    g_q2);
    cudaGetSymbolAddress((void**)&kv2,   g_kv2);
    cudaGetSymbolAddress((void**)&co1,   g_co1);
    cudaGetSymbolAddress((void**)&co2,   g_co2);
    cudaGetSymbolAddress((void**)&sk2,   g_skip2);
    cudaGetSymbolAddress((void**)&ffh,   g_ffh);
    cudaGetSymbolAddress((void**)&ffo,   g_ffo);
    cudaGetSymbolAddress((void**)&tmwt,  g_tmw_t);
    cudaGetSymbolAddress((void**)&qkvwt, g_qkvw_t);
    cudaGetSymbolAddress((void**)&wprwt, g_wprw_t);
    cudaGetSymbolAddress((void**)&caint, g_cain_t);
    cudaGetSymbolAddress((void**)&caoutt,g_caout_t);
    cudaGetSymbolAddress((void**)&ff1t,  g_ff1_t);
    cudaGetSymbolAddress((void**)&ff2t,  g_ff2_t);

    cudaFuncSetAttribute((const void*)tgemm<EPI_NONE,  __half>, cudaFuncAttributeMaxDynamicSharedMemorySize, TGEMM_SMEM);
    cudaFuncSetAttribute((const void*)tgemm<EPI_GELU,  __half>, cudaFuncAttributeMaxDynamicSharedMemorySize, TGEMM_SMEM);
    cudaFuncSetAttribute((const void*)tgemm<EPI_SCALE, __half>, cudaFuncAttributeMaxDynamicSharedMemorySize, TGEMM_SMEM);

    // batched weight transposes (+fp16 rounding)
    TWArgs twa;
    twa.seg[0] = { tm_w,     tmwt,   256,  512,    0 };
    twa.seg[1] = { qkv_w,    qkvwt,  512, 1536,  128 };
    twa.seg[2] = { wproj_w,  wprwt,  512,  512,  896 };
    twa.seg[3] = { ca_in_w,  caint,  512, 1536, 1152 };
    twa.seg[4] = { ca_out_w, caoutt, 512,  512, 1920 };
    twa.seg[5] = { ff_w1,    ff1t,   512, 2048, 2176 };
    twa.seg[6] = { ff_w2,    ff2t,  2048,  512, 3200 };
    twa.total = 4224;
    transpose_all<<<4224, 256>>>(twa);
    half_copy<<<512, 256>>>(vector, vin, 512 * 256);

    bias_kernel<<<T_ * T_, 256>>>(meta_w1, meta_b1, meta_w2, meta_b2);

    // vec = gelu(vector @ tm_w + tm_b)
    tgemm<EPI_GELU, __half><<<dim3(4, 4), 256, TGEMM_SMEM>>>(vin, tmwt, tm_b, vec, 512, 512, 256, 0.f);
    // K2|V2 fused
    tgemm<EPI_NONE, __half><<<dim3(8, 4), 256, TGEMM_SMEM>>>(vec, caint + 512 * 512, ca_in_b + 512, kv2, 512, 1024, 512, 0.f);

    unfold_kernel<<<NTOK, 256>>>(visual);
    tgemm<EPI_NONE, __half><<<dim3(12, 196), 256, TGEMM_SMEM>>>(tok, qkvwt, qkv_b, qkv, NTOK, 3 * CC, CC, 0.f);
    win_attn<<<BW_ * NH_, 256>>>(tau);
    tgemm<EPI_NONE, __half><<<dim3(4, 196), 256, TGEMM_SMEM>>>(o1, wprwt, wproj_b, w2, NTOK, CC, CC, 0.f);
    merge_ln1<<<BB * HWSZ, 256>>>(visual, ln1_g, ln1_b);
    tgemm<EPI_SCALE, __half><<<dim3(4, 196), 256, TGEMM_SMEM>>>(pq, caint, ca_in_b, q2, NTOK, CC, CC, 0.17677669529663687f);
    ca_attn<<<BW_ * NH_, 256>>>();
    tgemm<EPI_NONE, __half><<<dim3(4, 196), 256, TGEMM_SMEM>>>(co1, caoutt, ca_out_b, co2, NTOK, CC, CC, 0.f);
    ca_ln2<<<NTOK / 8, 256>>>(ln2_g, ln2_b);
    tgemm<EPI_GELU, __half><<<dim3(16, 196), 256, TGEMM_SMEM>>>(sk2, ff1t, ff_b1, ffh, NTOK, 4 * CC, CC, 0.f);
    tgemm<EPI_NONE, __half><<<dim3(4, 196), 256, TGEMM_SMEM>>>(ffh, ff2t, ff_b2, ffo, NTOK, CC, 2048, 0.f);
    final_kernel<<<BB * HWSZ, 256>>>(out, ln3_g, ln3_b);
}

// round 17
// speedup vs baseline: 1.1383x; 1.0061x over previous
#include <cuda_runtime.h>
#include <cuda_fp16.h>
#include <math.h>
#include <stdint.h>

// Problem constants
#define BB    8
#define CC    512
#define HH    56
#define WW_   56
#define HWSZ  3136
#define WS_   7
#define SS_   3
#define NH_   16
#define HD_   32
#define T_    49
#define NW_   64
#define BW_   512          // BB * NW_
#define NTOK  25088        // BW_ * T_
#define L_    64

// ---------------- scratch (device globals; no runtime alloc) ----------------
__device__ __align__(16) __half g_vin [512 * 256];
__device__ __align__(16) __half g_vec [BW_ * CC];
__device__ __align__(16) __half g_tok [NTOK * CC];
__device__ __align__(16) __half g_qkv [NTOK * 3 * CC];
__device__ __align__(16) __half g_o1  [NTOK * CC];
__device__ __align__(16) __half g_w2  [NTOK * CC];
__device__ __align__(16) __half g_skipa[NTOK * CC];     // skip1 fp16
__device__ __align__(16) __half g_pq  [NTOK * CC];
__device__ __align__(16) __half g_q2  [NTOK * CC];
__device__ __align__(16) __half g_kv2 [BW_ * 2 * CC];   // [B*L, 1024]: k | v
__device__ __align__(16) __half g_co1 [NTOK * CC];
__device__ __align__(16) __half g_co2 [NTOK * CC];
__device__ __align__(16) __half g_skip2[NTOK * CC];     // fp16 (GEMM A + residual)
__device__ __align__(16) __half g_ffh [NTOK * 4 * CC];
__device__ __align__(16) __half g_ffo [NTOK * CC];
__device__ float  g_bias[NH_ * T_ * T_];

// transposed (fp16) weights: [N, K] K-contiguous
__device__ __align__(16) __half g_tmw_t  [512 * 256];
__device__ __align__(16) __half g_qkvw_t [1536 * 512];
__device__ __align__(16) __half g_wprw_t [512 * 512];
__device__ __align__(16) __half g_cain_t [1536 * 512];
__device__ __align__(16) __half g_caout_t[512 * 512];
__device__ __align__(16) __half g_ff1_t  [2048 * 512];
__device__ __align__(16) __half g_ff2_t  [512 * 2048];

// ---------------- helpers ----------------
__device__ __forceinline__ float gelu_exact(float x) {
    return 0.5f * x * (1.0f + erff(x * 0.70710678118654752f));
}
__device__ __forceinline__ uint32_t s2u(const void* p) {
    uint32_t a;
    asm("{ .reg .u64 t; cvta.to.shared.u64 t, %1; cvt.u32.u64 %0, t; }"
        : "=r"(a) : "l"(p));
    return a;
}

__device__ __forceinline__ void block_meanvar(float s, float ss, int n,
                                              float* mu, float* rstd) {
    #pragma unroll
    for (int o = 16; o > 0; o >>= 1) {
        s  += __shfl_down_sync(0xffffffffu, s,  o);
        ss += __shfl_down_sync(0xffffffffu, ss, o);
    }
    __shared__ float rs[8], rss[8], res[2];
    int lane = threadIdx.x & 31, wid = threadIdx.x >> 5;
    if (lane == 0) { rs[wid] = s; rss[wid] = ss; }
    __syncthreads();
    if (threadIdx.x == 0) {
        float S = 0.f, SS2 = 0.f;
        #pragma unroll
        for (int i = 0; i < 8; i++) { S += rs[i]; SS2 += rss[i]; }
        float m = S / n;
        float var = SS2 / n - m * m;
        res[0] = m; res[1] = rsqrtf(var + 1e-5f);
    }
    __syncthreads();
    *mu = res[0]; *rstd = res[1];
}

__device__ __forceinline__ void warp_meanvar(float s, float ss, int n,
                                             float* mu, float* rstd) {
    #pragma unroll
    for (int o = 16; o > 0; o >>= 1) {
        s  += __shfl_xor_sync(0xffffffffu, s,  o);
        ss += __shfl_xor_sync(0xffffffffu, ss, o);
    }
    float m = s / n;
    *mu = m;
    *rstd = rsqrtf(ss / n - m * m + 1e-5f);
}

// load 8 fp16 (16B) -> 8 floats
__device__ __forceinline__ void h8_to_f(const __half* src, float* dst) {
    uint4 u = *(const uint4*)src;
    const __half2* h = (const __half2*)&u;
    #pragma unroll
    for (int i = 0; i < 4; i++) {
        float2 f = __half22float2(h[i]);
        dst[2 * i] = f.x; dst[2 * i + 1] = f.y;
    }
}

// ---------------- fp16 mma.sync GEMM (K-chunk 64, 3-stage + ldmatrix) -------
#define EPI_NONE  0
#define EPI_GELU  1
#define EPI_SCALE 2

#define LDPAD_H 72
#define TILEH (128 * LDPAD_H)            // halves per tile (64-K chunk)
#define TGEMM_SMEM (6 * TILEH * 2)       // 3 stages x (A+B), bytes = 110592

__device__ __forceinline__ void mma_f16(float* c, const uint32_t* a,
                                        const uint32_t* b) {
    asm volatile(
        "mma.sync.aligned.m16n8k16.row.col.f32.f16.f16.f32 "
        "{%0,%1,%2,%3}, {%4,%5,%6,%7}, {%8,%9}, {%0,%1,%2,%3};"
        : "+f"(c[0]), "+f"(c[1]), "+f"(c[2]), "+f"(c[3])
        : "r"(a[0]), "r"(a[1]), "r"(a[2]), "r"(a[3]),
          "r"(b[0]), "r"(b[1]));
}

#define LDSM_X4(r0, r1, r2, r3, addr) \
    asm volatile("ldmatrix.sync.aligned.m8n8.x4.shared.b16 {%0,%1,%2,%3}, [%4];" \
        : "=r"(r0), "=r"(r1), "=r"(r2), "=r"(r3) : "r"(addr))

__device__ __forceinline__ void store2(float* p, float a, float b) {
    *(float2*)p = make_float2(a, b);
}
__device__ __forceinline__ void store2(__half* p, float a, float b) {
    *(__half2*)p = __floats2half2_rn(a, b);
}

template <int EPI, typename OutT>
__global__ __launch_bounds__(256, 2)
void tgemm(const __half* __restrict__ A, const __half* __restrict__ W,
           const float* __restrict__ bias, OutT* __restrict__ C,
           int M, int N, int K, float alpha) {
    extern __shared__ __half smh[];
    __half* Abuf = smh;                  // [3][128][LDPAD_H]
    __half* Bbuf = smh + 3 * TILEH;      // [3][128][LDPAD_H]
    const uint32_t sm_a = s2u(Abuf), sm_b = s2u(Bbuf);

    const int tid = threadIdx.x;
    const int wid = tid >> 5, lane = tid & 31;
    const int m0 = blockIdx.y << 7, n0 = blockIdx.x << 7;
    const int wm = wid & 3, wn = wid >> 2;
    const int m_off = wm << 5;           // 32-row warp tile
    const int n_off = wn << 6;           // 64-col warp tile

    const __half* Abase = A + (size_t)m0 * K;
    const __half* Wbase = W + (size_t)n0 * K;
    const int NC = K >> 6;               // 64-K chunks

    const int seg = tid & 7;             // 8 x 16B (8-half) segments per row
    const int lr0 = tid >> 3;            // 0..31

    auto load_chunk = [&](int c, int sel) {
        uint32_t ab = sm_a + sel * (TILEH * 2);
        uint32_t bb = sm_b + sel * (TILEH * 2);
        const __half* As = Abase + c * 64 + seg * 8;
        const __half* Ws = Wbase + c * 64 + seg * 8;
        #pragma unroll
        for (int i = 0; i < 4; i++) {
            int r = lr0 + (i << 5);      // 0..127
            uint32_t so = (uint32_t)(r * (LDPAD_H * 2) + seg * 16);
            asm volatile("cp.async.cg.shared.global [%0], [%1], 16;"
                         :: "r"(ab + so), "l"(As + (size_t)r * K));
            asm volatile("cp.async.cg.shared.global [%0], [%1], 16;"
                         :: "r"(bb + so), "l"(Ws + (size_t)r * K));
        }
        asm volatile("cp.async.commit_group;" ::: "memory");
    };

    const int lm = lane >> 3, lr = lane & 7;
    uint32_t a_off[2], b_off[4];
    #pragma unroll
    for (int mt = 0; mt < 2; mt++) {
        int row = m_off + mt * 16 + lr + (lm & 1) * 8;
        int koff = (lm >> 1) * 8;
        a_off[mt] = (uint32_t)((row * LDPAD_H + koff) * 2);
    }
    #pragma unroll
    for (int g = 0; g < 4; g++) {
        int row = n_off + (2 * g + (lm >> 1)) * 8 + lr;
        int koff = (lm & 1) * 8;
        b_off[g] = (uint32_t)((row * LDPAD_H + koff) * 2);
    }

    float acc[2][8][4];
    #pragma unroll
    for (int i = 0; i < 2; i++)
        #pragma unroll
        for (int j = 0; j < 8; j++)
            #pragma unroll
            for (int q = 0; q < 4; q++) acc[i][j][q] = 0.f;

    // prefetch 2 chunks (3-stage ring, distance 2)
    load_chunk(0, 0);
    if (NC > 1) load_chunk(1, 1);

    const int qr = lane >> 2, qc = lane & 3;
    int sel = 0;

    for (int c = 0; c < NC; c++) {
        if (c + 1 < NC)
            asm volatile("cp.async.wait_group 1;" ::: "memory");
        else
            asm volatile("cp.async.wait_group 0;" ::: "memory");
        // all warps finished chunk c-1's reads; buffer (sel+2)%3 is free
        __syncthreads();
        if (c + 2 < NC) {
            int s2 = sel + 2; if (s2 >= 3) s2 -= 3;
            load_chunk(c + 2, s2);
        }

        const uint32_t abase = sm_a + sel * (TILEH * 2);
        const uint32_t bbase = sm_b + sel * (TILEH * 2);

        #pragma unroll
        for (int ks = 0; ks < 4; ks++) {
            const uint32_t kb = ks * 32;      // 16 halves = 32 bytes
            uint32_t a[2][4], b[8][2];
            #pragma unroll
            for (int mt = 0; mt < 2; mt++)
                LDSM_X4(a[mt][0], a[mt][1], a[mt][2], a[mt][3],
                        abase + a_off[mt] + kb);
            #pragma unroll
            for (int g = 0; g < 4; g++)
                LDSM_X4(b[2 * g][0], b[2 * g][1], b[2 * g + 1][0], b[2 * g + 1][1],
                        bbase + b_off[g] + kb);
            #pragma unroll
            for (int mt = 0; mt < 2; mt++)
                #pragma unroll
                for (int nt = 0; nt < 8; nt++)
                    mma_f16(acc[mt][nt], a[mt], b[nt]);
        }
        if (++sel >= 3) sel = 0;
    }

    #pragma unroll
    for (int mt = 0; mt < 2; mt++) {
        #pragma unroll
        for (int half = 0; half < 2; half++) {
            int row = m0 + m_off + mt * 16 + qr + half * 8;
            OutT* Cp = C + (size_t)row * N + n0 + n_off;
            #pragma unroll
            for (int nt = 0; nt < 8; nt++) {
                int col = nt * 8 + qc * 2;
                float v0 = acc[mt][nt][half * 2 + 0] + bias[n0 + n_off + col];
                float v1 = acc[mt][nt][half * 2 + 1] + bias[n0 + n_off + col + 1];
                if (EPI == EPI_GELU)  { v0 = gelu_exact(v0); v1 = gelu_exact(v1); }
                if (EPI == EPI_SCALE) { v0 *= alpha; v1 *= alpha; }
                store2(Cp + col, v0, v1);
            }
        }
    }
}

// ---------------- batched weight transpose + fp16 ----------------
struct TWSeg { const float* src; __half* dst; int K; int N; int tile0; };
struct TWArgs { TWSeg seg[7]; int total; };

__global__ __launch_bounds__(256)
void transpose_all(TWArgs a) {
    int bid = blockIdx.x;
    int si = 0;
    #pragma unroll
    for (int i = 1; i < 7; i++)
        if (bid >= a.seg[i].tile0) si = i;
    const TWSeg sg = a.seg[si];
    int local = bid - sg.tile0;
    int tilesX = sg.N >> 5;
    int nb = (local % tilesX) << 5;
    int kb = (local / tilesX) << 5;

    __shared__ float tile[32][33];
    int tx = threadIdx.x & 31, ty = threadIdx.x >> 5;
    #pragma unroll
    for (int i = 0; i < 32; i += 8)
        tile[ty + i][tx] = sg.src[(size_t)(kb + ty + i) * sg.N + nb + tx];
    __syncthreads();
    #pragma unroll
    for (int i = 0; i < 32; i += 8)
        sg.dst[(size_t)(nb + ty + i) * sg.K + kb + tx] =
            __float2half_rn(tile[tx][ty + i]);
}

__global__ void half_copy(const float* __restrict__ in, __half* __restrict__ o, int n) {
    int i = blockIdx.x * 256 + threadIdx.x;
    if (i < n) o[i] = __float2half_rn(in[i]);
}

// ---------------- relative-position bias precompute ----------------
__global__ void bias_kernel(const float* __restrict__ w1, const float* __restrict__ b1,
                            const float* __restrict__ w2, const float* __restrict__ b2) {
    int pair = blockIdx.x;
    int q = pair / T_, k = pair % T_;
    float d0 = (float)(q / WS_ - k / WS_);
    float d1 = (float)(q % WS_ - k % WS_);
    float r0 = (d0 > 0.f ? 1.f : (d0 < 0.f ? -1.f : 0.f)) * log1pf(fabsf(d0));
    float r1 = (d1 > 0.f ? 1.f : (d1 < 0.f ? -1.f : 0.f)) * log1pf(fabsf(d1));
    int tid = threadIdx.x;
    __shared__ float hbuf[256];
    float hv = r0 * w1[tid] + r1 * w1[256 + tid] + b1[tid];
    hbuf[tid] = fmaxf(hv, 0.f);
    __syncthreads();
    if (tid < NH_) {
        float s = b2[tid];
        #pragma unroll 8
        for (int j = 0; j < 256; j++) s += hbuf[j] * w2[j * NH_ + tid];
        g_bias[tid * (T_ * T_) + pair] = s;
    }
}

// ---------------- roll(-3,-3) + unfold into token rows (fp16) ---------------
__global__ __launch_bounds__(256)
void unfold_kernel(const float* __restrict__ visual) {
    int r = blockIdx.x;
    int bw = r / T_, t = r % T_;
    int b = bw / NW_, win = bw % NW_, wh = win >> 3, ww = win & 7;
    int h = (wh * WS_ + t / WS_ + SS_) % HH;
    int w = (ww * WS_ + t % WS_ + SS_) % WW_;
    int hw = h * WW_ + w;
    for (int c = threadIdx.x; c < CC; c += 256)
        g_tok[(size_t)r * CC + c] = __float2half_rn(visual[(size_t)(b * CC + c) * HWSZ + hw]);
}

// ---------------- window attention (register-blocked, vector loads) ---------
#define SQS 36   // padded row stride (floats)
__global__ __launch_bounds__(256)
void win_attn(const float* __restrict__ tau) {
    int bw = blockIdx.x >> 4;
    int hh = blockIdx.x & 15;
    int tid = threadIdx.x;

    __shared__ __align__(16) float sq[52 * SQS], sk[52 * SQS], sv[52 * SQS];
    __shared__ float ss[50 * 50];
    __shared__ float nq[52], nk[52];
    __shared__ int   rg[T_];

    for (int i = tid; i < 3 * 32; i += 256) {
        int r = 49 + i / 32, c = i % 32;
        sq[r * SQS + c] = 0.f; sk[r * SQS + c] = 0.f; sv[r * SQS + c] = 0.f;
    }

    if (tid < T_ * 4) {
        int t = tid >> 2, sg = tid & 3;
        size_t ro = (size_t)(bw * T_ + t) * (3 * CC) + hh * HD_ + sg * 8;
        h8_to_f(g_qkv + ro,           &sq[t * SQS + sg * 8]);
        h8_to_f(g_qkv + ro + CC,      &sk[t * SQS + sg * 8]);
        h8_to_f(g_qkv + ro + 2 * CC,  &sv[t * SQS + sg * 8]);
    }
    int win = bw & 63, wh = win >> 3, ww = win & 7;
    if (tid < T_) {
        int row = wh * WS_ + tid / WS_;
        int col = ww * WS_ + tid % WS_;
        int rh = row < 49 ? 0 : (row < 53 ? 1 : 2);
        int rw = col < 49 ? 0 : (col < 53 ? 1 : 2);
        rg[tid] = rh * 3 + rw;
    }
    __syncthreads();

    if (tid < 52) {
        if (tid < T_) {
            float s1 = 0.f, s2 = 0.f;
            #pragma unroll
            for (int d = 0; d < HD_; d++) {
                float a = sq[tid * SQS + d], b = sk[tid * SQS + d];
                s1 += a * a; s2 += b * b;
            }
            nq[tid] = sqrtf(s1); nk[tid] = sqrtf(s2);
        } else {
            nq[tid] = 1.f; nk[tid] = 1.f;
        }
    }
    __syncthreads();

    float tauh = fmaxf(tau[hh], 0.01f);
    const float* bh = &g_bias[hh * (T_ * T_)];
    if (tid < 169) {
        int q0 = (tid / 13) * 4, k0 = (tid % 13) * 4;
        float acc[4][4];
        #pragma unroll
        for (int i = 0; i < 4; i++)
            #pragma unroll
            for (int j = 0; j < 4; j++) acc[i][j] = 0.f;
        #pragma unroll
        for (int d4 = 0; d4 < 8; d4++) {
            float4 qv[4], kv[4];
            #pragma unroll
            for (int i = 0; i < 4; i++)
                qv[i] = *(const float4*)&sq[(q0 + i) * SQS + d4 * 4];
            #pragma unroll
            for (int j = 0; j < 4; j++)
                kv[j] = *(const float4*)&sk[(k0 + j) * SQS + d4 * 4];
            #pragma unroll
            for (int i = 0; i < 4; i++)
                #pragma unroll
                for (int j = 0; j < 4; j++)
                    acc[i][j] += qv[i].x * kv[j].x + qv[i].y * kv[j].y
                               + qv[i].z * kv[j].z + qv[i].w * kv[j].w;
        }
        #pragma unroll
        for (int i = 0; i < 4; i++) {
            int q = q0 + i;
            if (q >= T_) break;
            #pragma unroll
            for (int j = 0; j < 4; j++) {
                int k = k0 + j;
                if (k >= T_) continue;
                float s = acc[i][j] / fmaxf(nq[q] * nk[k], 1e-6f) / tauh
                        + bh[q * T_ + k];
                if (rg[q] != rg[k]) s -= 100.0f;
                ss[q * 50 + k] = s;
            }
        }
    }
    __syncthreads();

    if (tid < T_) {
        float m = -1e30f;
        for (int k = 0; k < T_; k++) m = fmaxf(m, ss[tid * 50 + k]);
        float sum = 0.f;
        for (int k = 0; k < T_; k++) {
            float e = expf(ss[tid * 50 + k] - m);
            ss[tid * 50 + k] = e; sum += e;
        }
        float inv = 1.f / sum;
        for (int k = 0; k < T_; k++) ss[tid * 50 + k] *= inv;
    }
    __syncthreads();

    if (tid < 200) {
        int t0 = (tid / 8) * 2, d4 = tid % 8;
        float4 a0 = make_float4(0.f, 0.f, 0.f, 0.f), a1 = a0;
        for (int k = 0; k < T_; k++) {
            float s0 = ss[t0 * 50 + k];
            float s1 = ss[(t0 + 1) * 50 + k];
            float4 v = *(const float4*)&sv[k * SQS + d4 * 4];
            a0.x += s0 * v.x; a0.y += s0 * v.y; a0.z += s0 * v.z; a0.w += s0 * v.w;
            a1.x += s1 * v.x; a1.y += s1 * v.y; a1.z += s1 * v.z; a1.w += s1 * v.w;
        }
        __half* op = g_o1 + (size_t)(bw * T_ + t0) * CC + hh * HD_ + d4 * 4;
        ((__half2*)op)[0] = __floats2half2_rn(a0.x, a0.y);
        ((__half2*)op)[1] = __floats2half2_rn(a0.z, a0.w);
        if (t0 + 1 < T_) {
            __half* op1 = op + CC;
            ((__half2*)op1)[0] = __floats2half2_rn(a1.x, a1.y);
            ((__half2*)op1)[1] = __floats2half2_rn(a1.z, a1.w);
        }
    }
}

// ---------------- fold+roll(+3) + LN1 + residual; emit CA query tokens ------
__global__ __launch_bounds__(256)
void merge_ln1(const float* __restrict__ visual,
               const float* __restrict__ g, const float* __restrict__ bt) {
    int pos = blockIdx.x;
    int b = pos / HWSZ, hw = pos % HWSZ;
    int h = hw / WW_, w = hw % WW_;
    int hp = (h + HH - SS_) % HH, wp = (w + WW_ - SS_) % WW_;
    int rm = (b * NW_ + (hp / WS_) * 8 + (wp / WS_)) * T_ + (hp % WS_) * WS_ + (wp % WS_);

    __shared__ float x[CC];
    int tid = threadIdx.x;
    float s = 0.f, ss2 = 0.f;
    for (int c = tid; c < CC; c += 256) {
        float v = __half2float(g_w2[(size_t)rm * CC + c]);
        x[c] = v; s += v; ss2 += v * v;
    }
    float mu, rstd;
    block_meanvar(s, ss2, CC, &mu, &rstd);
    for (int c = tid; c < CC; c += 256) {
        float v = (x[c] - mu) * rstd * g[c] + bt[c]
                + visual[(size_t)(b * CC + c) * HWSZ + hw];
        __half hv = __float2half_rn(v);
        g_skipa[(size_t)pos * CC + c] = hv;
        g_pq  [(size_t)rm  * CC + c] = hv;
    }
}

// ---------------- cross attention (register-blocked, vector loads) ----------
__global__ __launch_bounds__(256)
void ca_attn() {
    int bw = blockIdx.x >> 4;
    int hh = blockIdx.x & 15;
    int bkv = bw & 7;
    int tid = threadIdx.x;

    __shared__ __align__(16) float sq[52 * SQS], sk[L_ * SQS], sv[L_ * SQS];
    __shared__ float ss[50 * 65];

    for (int i = tid; i < 3 * 32; i += 256) {
        int r = 49 + i / 32, c = i % 32;
        sq[r * SQS + c] = 0.f;
    }
    if (tid < T_ * 4) {
        int t = tid >> 2, sg = tid & 3;
        h8_to_f(g_q2 + (size_t)(bw * T_ + t) * CC + hh * HD_ + sg * 8,
                &sq[t * SQS + sg * 8]);
    }
    {
        int l = tid >> 2, sg = tid & 3;      // 256 = 64*4 exactly
        size_t ro = (size_t)(bkv * L_ + l) * (2 * CC) + hh * HD_ + sg * 8;
        h8_to_f(g_kv2 + ro,      &sk[l * SQS + sg * 8]);
        h8_to_f(g_kv2 + ro + CC, &sv[l * SQS + sg * 8]);
    }
    __syncthreads();

    if (tid < 208) {
        int q0 = (tid / 16) * 4, l0 = (tid % 16) * 4;
        float acc[4][4];
        #pragma unroll
        for (int i = 0; i < 4; i++)
            #pragma unroll
            for (int j = 0; j < 4; j++) acc[i][j] = 0.f;
        #pragma unroll
        for (int d4 = 0; d4 < 8; d4++) {
            float4 qv[4], kv[4];
            #pragma unroll
            for (int i = 0; i < 4; i++)
                qv[i] = *(const float4*)&sq[(q0 + i) * SQS + d4 * 4];
            #pragma unroll
            for (int j = 0; j < 4; j++)
                kv[j] = *(const float4*)&sk[(l0 + j) * SQS + d4 * 4];
            #pragma unroll
            for (int i = 0; i < 4; i++)
                #pragma unroll
                for (int j = 0; j < 4; j++)
                    acc[i][j] += qv[i].x * kv[j].x + qv[i].y * kv[j].y
                               + qv[i].z * kv[j].z + qv[i].w * kv[j].w;
        }
        #pragma unroll
        for (int i = 0; i < 4; i++) {
            int q = q0 + i;
            if (q >= T_) break;
            #pragma unroll
            for (int j = 0; j < 4; j++)
                ss[q * 65 + l0 + j] = acc[i][j];
        }
    }
    __syncthreads();

    if (tid < T_) {
        float m = -1e30f;
        for (int l = 0; l < L_; l++) m = fmaxf(m, ss[tid * 65 + l]);
        float sum = 0.f;
        for (int l = 0; l < L_; l++) {
            float e = expf(ss[tid * 65 + l] - m);
            ss[tid * 65 + l] = e; sum += e;
        }
        float inv = 1.f / sum;
        for (int l = 0; l < L_; l++) ss[tid * 65 + l] *= inv;
    }
    __syncthreads();

    if (tid < 200) {
        int t0 = (tid / 8) * 2, d4 = tid % 8;
        float4 a0 = make_float4(0.f, 0.f, 0.f, 0.f), a1 = a0;
        for (int l = 0; l < L_; l++) {
            float s0 = ss[t0 * 65 + l];
            float s1 = ss[(t0 + 1) * 65 + l];
            float4 v = *(const float4*)&sv[l * SQS + d4 * 4];
            a0.x += s0 * v.x; a0.y += s0 * v.y; a0.z += s0 * v.z; a0.w += s0 * v.w;
            a1.x += s1 * v.x; a1.y += s1 * v.y; a1.z += s1 * v.z; a1.w += s1 * v.w;
        }
        __half* op = g_co1 + (size_t)(bw * T_ + t0) * CC + hh * HD_ + d4 * 4;
        ((__half2*)op)[0] = __floats2half2_rn(a0.x, a0.y);
        ((__half2*)op)[1] = __floats2half2_rn(a0.z, a0.w);
        if (t0 + 1 < T_) {
            __half* op1 = op + CC;
            ((__half2*)op1)[0] = __floats2half2_rn(a1.x, a1.y);
            ((__half2*)op1)[1] = __floats2half2_rn(a1.z, a1.w);
        }
    }
}

// ---------------- LN2 + fold+roll(+3) + residual (warp-per-row, coalesced) --
__global__ __launch_bounds__(256)
void ca_ln2(const float* __restrict__ g, const float* __restrict__ bt) {
    int r = blockIdx.x * 8 + (threadIdx.x >> 5);
    int lane = threadIdx.x & 31;
    int bw = r / T_, t = r % T_;
    int b = bw / NW_, win = bw % NW_, wh = win >> 3, ww = win & 7;
    int h = (wh * WS_ + t / WS_ + SS_) % HH;
    int w = (ww * WS_ + t % WS_ + SS_) % WW_;
    int pos = b * HWSZ + h * WW_ + w;

    int c0 = lane * 16;
    float x[16];
    h8_to_f(g_co2 + (size_t)r * CC + c0,     x);
    h8_to_f(g_co2 + (size_t)r * CC + c0 + 8, x + 8);

    float s = 0.f, ss = 0.f;
    #pragma unroll
    for (int i = 0; i < 16; i++) { s += x[i]; ss += x[i] * x[i]; }
    float mu, rstd;
    warp_meanvar(s, ss, CC, &mu, &rstd);

    float sa[16];
    h8_to_f(g_skipa + (size_t)pos * CC + c0,     sa);
    h8_to_f(g_skipa + (size_t)pos * CC + c0 + 8, sa + 8);

    __half* sp = g_skip2 + (size_t)pos * CC + c0;
    #pragma unroll
    for (int i = 0; i < 16; i += 2) {
        float v0 = (x[i]     - mu) * rstd * g[c0 + i]     + bt[c0 + i]     + sa[i];
        float v1 = (x[i + 1] - mu) * rstd * g[c0 + i + 1] + bt[c0 + i + 1] + sa[i + 1];
        *(__half2*)(sp + i) = __floats2half2_rn(v0, v1);
    }
}

// ---------------- LN3(ff) + skip2, write [B,C,H,W] ----------------
__global__ __launch_bounds__(256)
void final_kernel(float* __restrict__ out,
                  const float* __restrict__ g, const float* __restrict__ bt) {
    int pos = blockIdx.x;
    int b = pos / HWSZ, hw = pos % HWSZ;

    __shared__ float x[CC];
    int tid = threadIdx.x;
    float s = 0.f, ss2 = 0.f;
    for (int c = tid; c < CC; c += 256) {
        float v = __half2float(g_ffo[(size_t)pos * CC + c]);
        x[c] = v; s += v; ss2 += v * v;
    }
    float mu, rstd;
    block_meanvar(s, ss2, CC, &mu, &rstd);
    for (int c = tid; c < CC; c += 256) {
        float v = (x[c] - mu) * rstd * g[c] + bt[c];
        out[(size_t)(b * CC + c) * HWSZ + hw] =
            __half2float(g_skip2[(size_t)pos * CC + c]) + v;
    }
}

// ---------------- launch ----------------
extern "C" void kernel_launch(void* const* d_in, const int* in_sizes, int n_in,
                              void* d_out, int out_size) {
    const float* visual   = (const float*)d_in[0];
    const float* vector   = (const float*)d_in[1];
    const float* tm_w     = (const float*)d_in[2];
    const float* tm_b     = (const float*)d_in[3];
    const float* ln1_g    = (const float*)d_in[4];
    const float* ln1_b    = (const float*)d_in[5];
    const float* ln2_g    = (const float*)d_in[6];
    const float* ln2_b    = (const float*)d_in[7];
    const float* ln3_g    = (const float*)d_in[8];
    const float* ln3_b    = (const float*)d_in[9];
    const float* qkv_w    = (const float*)d_in[10];
    const float* qkv_b    = (const float*)d_in[11];
    const float* wproj_w  = (const float*)d_in[12];
    const float* wproj_b  = (const float*)d_in[13];
    const float* meta_w1  = (const float*)d_in[14];
    const float* meta_b1  = (const float*)d_in[15];
    const float* meta_w2  = (const float*)d_in[16];
    const float* meta_b2  = (const float*)d_in[17];
    const float* tau      = (const float*)d_in[18];
    const float* ca_in_w  = (const float*)d_in[19];
    const float* ca_in_b  = (const float*)d_in[20];
    const float* ca_out_w = (const float*)d_in[21];
    const float* ca_out_b = (const float*)d_in[22];
    const float* ff_w1    = (const float*)d_in[23];
    const float* ff_b1    = (const float*)d_in[24];
    const float* ff_w2    = (const float*)d_in[25];
    const float* ff_b2    = (const float*)d_in[26];
    float* out = (float*)d_out;

    __half *vin, *vec, *tok, *o1, *pq, *co1, *sk2, *ffh;
    __half *qkv, *w2, *q2, *kv2, *co2, *ffo;
    __half *tmwt, *qkvwt, *wprwt, *caint, *caoutt, *ff1t, *ff2t;
    cudaGetSymbolAddress((void**)&vin,   g_vin);
    cudaGetSymbolAddress((void**)&vec,   g_vec);
    cudaGetSymbolAddress((void**)&tok,   g_tok);
    cudaGetSymbolAddress((void**)&qkv,   g_qkv);
    cudaGetSymbolAddress((void**)&o1,    g_o1);
    cudaGetSymbolAddress((void**)&w2,    g_w2);
    cudaGetSymbolAddress((void**)&pq,    g_pq);
    cudaGetSymbolAddress((void**)&q2,    g_q2);
    cudaGetSymbolAddress((void**)&kv2,   g_kv2);
    cudaGetSymbolAddress((void**)&co1,   g_co1);
    cudaGetSymbolAddress((void**)&co2,   g_co2);
    cudaGetSymbolAddress((void**)&sk2,   g_skip2);
    cudaGetSymbolAddress((void**)&ffh,   g_ffh);
    cudaGetSymbolAddress((void**)&ffo,   g_ffo);
    cudaGetSymbolAddress((void**)&tmwt,  g_tmw_t);
    cudaGetSymbolAddress((void**)&qkvwt, g_qkvw_t);
    cudaGetSymbolAddress((void**)&wprwt, g_wprw_t);
    cudaGetSymbolAddress((void**)&caint, g_cain_t);
    cudaGetSymbolAddress((void**)&caoutt,g_caout_t);
    cudaGetSymbolAddress((void**)&ff1t,  g_ff1_t);
    cudaGetSymbolAddress((void**)&ff2t,  g_ff2_t);

    cudaFuncSetAttribute((const void*)tgemm<EPI_NONE,  __half>, cudaFuncAttributeMaxDynamicSharedMemorySize, TGEMM_SMEM);
    cudaFuncSetAttribute((const void*)tgemm<EPI_GELU,  __half>, cudaFuncAttributeMaxDynamicSharedMemorySize, TGEMM_SMEM);
    cudaFuncSetAttribute((const void*)tgemm<EPI_SCALE, __half>, cudaFuncAttributeMaxDynamicSharedMemorySize, TGEMM_SMEM);

    // batched weight transposes (+fp16 rounding)
    TWArgs twa;
    twa.seg[0] = { tm_w,     tmwt,   256,  512,    0 };
    twa.seg[1] = { qkv_w,    qkvwt,  512, 1536,  128 };
    twa.seg[2] = { wproj_w,  wprwt,  512,  512,  896 };
    twa.seg[3] = { ca_in_w,  caint,  512, 1536, 1152 };
    twa.seg[4] = { ca_out_w, caoutt, 512,  512, 1920 };
    twa.seg[5] = { ff_w1,    ff1t,   512, 2048, 2176 };
    twa.seg[6] = { ff_w2,    ff2t,  2048,  512, 3200 };
    twa.total = 4224;
    transpose_all<<<4224, 256>>>(twa);
    half_copy<<<512, 256>>>(vector, vin, 512 * 256);

    bias_kernel<<<T_ * T_, 256>>>(meta_w1, meta_b1, meta_w2, meta_b2);

    // vec = gelu(vector @ tm_w + tm_b)
    tgemm<EPI_GELU, __half><<<dim3(4, 4), 256, TGEMM_SMEM>>>(vin, tmwt, tm_b, vec, 512, 512, 256, 0.f);
    // K2|V2 fused
    tgemm<EPI_NONE, __half><<<dim3(8, 4), 256, TGEMM_SMEM>>>(vec, caint + 512 * 512, ca_in_b + 512, kv2, 512, 1024, 512, 0.f);

    unfold_kernel<<<NTOK, 256>>>(visual);
    tgemm<EPI_NONE, __half><<<dim3(12, 196), 256, TGEMM_SMEM>>>(tok, qkvwt, qkv_b, qkv, NTOK, 3 * CC, CC, 0.f);
    win_attn<<<BW_ * NH_, 256>>>(tau);
    tgemm<EPI_NONE, __half><<<dim3(4, 196), 256, TGEMM_SMEM>>>(o1, wprwt, wproj_b, w2, NTOK, CC, CC, 0.f);
    merge_ln1<<<BB * HWSZ, 256>>>(visual, ln1_g, ln1_b);
    tgemm<EPI_SCALE, __half><<<dim3(4, 196), 256, TGEMM_SMEM>>>(pq, caint, ca_in_b, q2, NTOK, CC, CC, 0.17677669529663687f);
    ca_attn<<<BW_ * NH_, 256>>>();
    tgemm<EPI_NONE, __half><<<dim3(4, 196), 256, TGEMM_SMEM>>>(co1, caoutt, ca_out_b, co2, NTOK, CC, CC, 0.f);
    ca_ln2<<<NTOK / 8, 256>>>(ln2_g, ln2_b);
    tgemm<EPI_GELU, __half><<<dim3(16, 196), 256, TGEMM_SMEM>>>(sk2, ff1t, ff_b1, ffh, NTOK, 4 * CC, CC, 0.f);
    tgemm<EPI_NONE, __half><<<dim3(4, 196), 256, TGEMM_SMEM>>>(ffh, ff2t, ff_b2, ffo, NTOK, CC, 2048, 0.f);
    final_kernel<<<BB * HWSZ, 256>>>(out, ln3_g, ln3_b);
}